// round 3
// baseline (speedup 1.0000x reference)
#include <cuda_runtime.h>
#include <cuda_bf16.h>
#include <cstdint>

// Problem constants
#define BB 32
#define CC 128
#define NN 16384
#define KK 64
#define TN 64          // n-tile width
#define SPLITS 16      // n-splits per batch
#define TILES ((NN / SPLITS) / TN)   // 16 tiles per block
#define LDX 66         // padded leading dim for x tile  [128][66]
#define LDL 66         // padded leading dim for logits  [64][66]
#define EPSV 1e-12f

typedef unsigned long long u64;

// ---- packed f32x2 helpers (Blackwell FFMA2 path) --------------------------
__device__ __forceinline__ u64 pk2(float lo, float hi) {
    u64 r; asm("mov.b64 %0, {%1, %2};" : "=l"(r) : "f"(lo), "f"(hi)); return r;
}
__device__ __forceinline__ float2 up2(u64 v) {
    float2 f; asm("mov.b64 {%0, %1}, %2;" : "=f"(f.x), "=f"(f.y) : "l"(v)); return f;
}
__device__ __forceinline__ u64 fma2_(u64 a, u64 b, u64 c) {
    u64 d; asm("fma.rn.f32x2 %0, %1, %2, %3;" : "=l"(d) : "l"(a), "l"(b), "l"(c)); return d;
}
__device__ __forceinline__ u64 add2_(u64 a, u64 b) {
    u64 d; asm("add.rn.f32x2 %0, %1, %2;" : "=l"(d) : "l"(a), "l"(b)); return d;
}

// Scratch (allocation-free rule: __device__ globals)
__device__ float g_agg[BB * KK * CC];   // 1 MB
__device__ float g_asum[BB * KK];

// ---------------------------------------------------------------------------
__global__ void zero_scratch() {
    int i = blockIdx.x * blockDim.x + threadIdx.x;
    const int tot = BB * KK * CC + BB * KK;
    for (; i < tot; i += gridDim.x * blockDim.x) {
        if (i < BB * KK * CC) g_agg[i] = 0.0f;
        else g_asum[i - BB * KK * CC] = 0.0f;
    }
}

// ---------------------------------------------------------------------------
// Fused: logits GEMM -> relu+softmax(K) -> aggregation GEMM (+ a row-sums)
// grid (SPLITS, BB), 256 threads
__global__ __launch_bounds__(256, 2) void netvlad_main(
    const float* __restrict__ x,
    const float* __restrict__ conv_w,
    const float* __restrict__ conv_b)
{
    extern __shared__ float smem[];
    float* sW = smem;                       // [64][128]   8192
    float* sB = sW + KK * CC;               // [64]          64
    float* sX = sB + KK;                    // [128][66]   8448
    float* sL = sX + CC * LDX;              // [64][66]    4224

    const int b     = blockIdx.y;
    const int split = blockIdx.x;
    const int t     = threadIdx.x;

    // Load conv_w / conv_b once
    for (int i = t; i < KK * CC; i += 256) sW[i] = conv_w[i];
    if (t < KK) sB[t] = conv_b[t];

    // Phase-1 mapping: 4k x 4n per thread
    const int ng1 = t & 15;        // n = ng1*4 + j
    const int kq1 = t >> 4;        // k = kq1*4 + i
    // Softmax mapping: 4 sub-threads per column
    const int col = t >> 2;
    const int sub = t & 3;
    // Phase-3 mapping: 4k x 8c per thread (c strided by 16 -> conflict-free)
    const int cg  = t & 15;        // c = cg + 16*j
    const int kq3 = t >> 4;        // k = kq3*4 + i

    // Packed accumulators: lo lane = even-n partial, hi lane = odd-n partial
    u64 vacc2[4][8];
    #pragma unroll
    for (int i = 0; i < 4; i++)
        #pragma unroll
        for (int j = 0; j < 8; j++) vacc2[i][j] = 0ull;
    u64 sacc2[4] = {0ull, 0ull, 0ull, 0ull};

    const int n_base0 = split * (NN / SPLITS);
    const float* xb = x + (size_t)b * CC * NN;

    __syncthreads();   // sW/sB ready

    for (int tile = 0; tile < TILES; tile++) {
        const int n0 = n_base0 + tile * TN;

        // ---- stage x tile: 128 rows x 64 floats, coalesced float4 ----
        {
            const int row_in = t >> 4;        // 0..15
            const int j4     = (t & 15) * 4;  // 0..60
            #pragma unroll
            for (int p = 0; p < 8; p++) {
                int c = p * 16 + row_in;
                float4 v = *(const float4*)(xb + (size_t)c * NN + n0 + j4);
                float* d = &sX[c * LDX + j4];
                d[0] = v.x; d[1] = v.y; d[2] = v.z; d[3] = v.w;
            }
        }
        __syncthreads();

        // ---- phase 1: logits[k][n] = sum_c w[k][c] * x[c][n]  (FFMA2) ----
        {
            // acc2[i][0] covers (n1, n1+1), acc2[i][1] covers (n1+2, n1+3)
            u64 acc2[4][2];
            #pragma unroll
            for (int i = 0; i < 4; i++) { acc2[i][0] = 0ull; acc2[i][1] = 0ull; }

            const int n1 = ng1 * 4;
            #pragma unroll 4
            for (int c = 0; c < CC; c += 2) {
                u64 xa0 = *(const u64*)&sX[c * LDX + n1];
                u64 xb0 = *(const u64*)&sX[c * LDX + n1 + 2];
                u64 xa1 = *(const u64*)&sX[(c + 1) * LDX + n1];
                u64 xb1 = *(const u64*)&sX[(c + 1) * LDX + n1 + 2];
                #pragma unroll
                for (int i = 0; i < 4; i++) {
                    float2 w2 = *(const float2*)&sW[(kq1 * 4 + i) * CC + c];
                    u64 p0 = pk2(w2.x, w2.x);
                    u64 p1 = pk2(w2.y, w2.y);
                    acc2[i][0] = fma2_(p0, xa0, acc2[i][0]);
                    acc2[i][1] = fma2_(p0, xb0, acc2[i][1]);
                    acc2[i][0] = fma2_(p1, xa1, acc2[i][0]);
                    acc2[i][1] = fma2_(p1, xb1, acc2[i][1]);
                }
            }
            #pragma unroll
            for (int i = 0; i < 4; i++) {
                float bias = sB[kq1 * 4 + i];
                float2 lo = up2(acc2[i][0]);
                float2 hi = up2(acc2[i][1]);
                float* dst = &sL[(kq1 * 4 + i) * LDL + n1];
                dst[0] = lo.x + bias;
                dst[1] = lo.y + bias;
                dst[2] = hi.x + bias;
                dst[3] = hi.y + bias;
            }
        }
        __syncthreads();

        // ---- phase 2: softmax(relu(logits)) over k, per column n ----
        {
            float e[16];
            float m = 0.0f;   // relu => max >= 0
            #pragma unroll
            for (int i = 0; i < 16; i++) {
                float v = sL[(sub + 4 * i) * LDL + col];
                v = fmaxf(v, 0.0f);
                e[i] = v;
                m = fmaxf(m, v);
            }
            m = fmaxf(m, __shfl_xor_sync(0xffffffffu, m, 1));
            m = fmaxf(m, __shfl_xor_sync(0xffffffffu, m, 2));
            float s = 0.0f;
            #pragma unroll
            for (int i = 0; i < 16; i++) {
                e[i] = __expf(e[i] - m);
                s += e[i];
            }
            s += __shfl_xor_sync(0xffffffffu, s, 1);
            s += __shfl_xor_sync(0xffffffffu, s, 2);
            float inv = 1.0f / s;
            #pragma unroll
            for (int i = 0; i < 16; i++)
                sL[(sub + 4 * i) * LDL + col] = e[i] * inv;
        }
        __syncthreads();

        // ---- phase 3: vacc[k][c] += sum_n a[k][n]*x[c][n]  (FFMA2, lo/hi
        //      lanes hold even/odd-n partial sums) ----
        {
            #pragma unroll 2
            for (int n = 0; n < TN; n += 2) {
                u64 a2[4];
                #pragma unroll
                for (int i = 0; i < 4; i++)
                    a2[i] = *(const u64*)&sL[(kq3 * 4 + i) * LDL + n];
                u64 x2[8];
                #pragma unroll
                for (int j = 0; j < 8; j++)
                    x2[j] = *(const u64*)&sX[(cg + 16 * j) * LDX + n];
                #pragma unroll
                for (int i = 0; i < 4; i++)
                    #pragma unroll
                    for (int j = 0; j < 8; j++)
                        vacc2[i][j] = fma2_(a2[i], x2[j], vacc2[i][j]);
                if (cg == 0) {
                    #pragma unroll
                    for (int i = 0; i < 4; i++)
                        sacc2[i] = add2_(sacc2[i], a2[i]);
                }
            }
        }
        __syncthreads();
    }

    // ---- accumulate partials to global ----
    float* agg = g_agg + (size_t)b * KK * CC;
    #pragma unroll
    for (int i = 0; i < 4; i++) {
        int k = kq3 * 4 + i;
        #pragma unroll
        for (int j = 0; j < 8; j++) {
            int c = cg + 16 * j;
            float2 f = up2(vacc2[i][j]);
            atomicAdd(&agg[k * CC + c], f.x + f.y);
        }
    }
    if (cg == 0) {
        #pragma unroll
        for (int i = 0; i < 4; i++) {
            float2 f = up2(sacc2[i]);
            atomicAdd(&g_asum[b * KK + kq3 * 4 + i], f.x + f.y);
        }
    }
}

// ---------------------------------------------------------------------------
// Finalize: residual vs centroids, intra-norm (over C), global norm (over K*C)
// grid (BB), 256 threads (8 warps, each warp: 8 rows)
__global__ __launch_bounds__(256) void netvlad_finalize(
    const float* __restrict__ centroids,
    float* __restrict__ out)
{
    __shared__ float sred[8];
    const int b = blockIdx.x;
    const int t = threadIdx.x;
    const int lane = t & 31;
    const int w = t >> 5;

    const float* agg = g_agg + (size_t)b * KK * CC;
    const float* as  = g_asum + b * KK;

    float v[8][4];
    float gss = 0.0f;

    #pragma unroll
    for (int r = 0; r < 8; r++) {
        const int k = w * 8 + r;
        const float s = as[k];
        const int c4 = lane * 4;
        float4 a = *(const float4*)&agg[k * CC + c4];
        float4 cn = *(const float4*)&centroids[k * CC + c4];
        v[r][0] = a.x - s * cn.x;
        v[r][1] = a.y - s * cn.y;
        v[r][2] = a.z - s * cn.z;
        v[r][3] = a.w - s * cn.w;
        float ss = v[r][0]*v[r][0] + v[r][1]*v[r][1] + v[r][2]*v[r][2] + v[r][3]*v[r][3];
        #pragma unroll
        for (int off = 16; off > 0; off >>= 1)
            ss += __shfl_xor_sync(0xffffffffu, ss, off);
        float scale = 1.0f / fmaxf(sqrtf(ss), EPSV);
        #pragma unroll
        for (int j = 0; j < 4; j++) {
            v[r][j] *= scale;
            gss += v[r][j] * v[r][j];
        }
    }

    #pragma unroll
    for (int off = 16; off > 0; off >>= 1)
        gss += __shfl_xor_sync(0xffffffffu, gss, off);
    if (lane == 0) sred[w] = gss;
    __syncthreads();
    float tot = 0.0f;
    #pragma unroll
    for (int i = 0; i < 8; i++) tot += sred[i];
    float gscale = 1.0f / fmaxf(sqrtf(tot), EPSV);

    #pragma unroll
    for (int r = 0; r < 8; r++) {
        const int k = w * 8 + r;
        float4 o;
        o.x = v[r][0] * gscale;
        o.y = v[r][1] * gscale;
        o.z = v[r][2] * gscale;
        o.w = v[r][3] * gscale;
        *(float4*)&out[(size_t)b * KK * CC + k * CC + lane * 4] = o;
    }
}

// ---------------------------------------------------------------------------
extern "C" void kernel_launch(void* const* d_in, const int* in_sizes, int n_in,
                              void* d_out, int out_size)
{
    const float* x         = (const float*)d_in[0];
    const float* conv_w    = (const float*)d_in[1];
    const float* conv_b    = (const float*)d_in[2];
    const float* centroids = (const float*)d_in[3];
    float* out = (float*)d_out;

    const int smem_bytes = (KK * CC + KK + CC * LDX + KK * LDL) * (int)sizeof(float);
    static bool attr_set = false;
    if (!attr_set) {
        cudaFuncSetAttribute(netvlad_main,
                             cudaFuncAttributeMaxDynamicSharedMemorySize,
                             smem_bytes);
        attr_set = true;
    }

    zero_scratch<<<264, 1024>>>();
    dim3 grid(SPLITS, BB);
    netvlad_main<<<grid, 256, smem_bytes>>>(x, conv_w, conv_b);
    netvlad_finalize<<<BB, 256>>>(centroids, out);
}

// round 4
// speedup vs baseline: 1.0002x; 1.0002x over previous
#include <cuda_runtime.h>
#include <cuda_bf16.h>
#include <cstdint>

// Problem constants
#define BB 32
#define CC 128
#define NN 16384
#define KK 64
#define TN 64          // n-tile width
#define SPLITS 16      // n-splits per batch
#define TILES ((NN / SPLITS) / TN)   // 16 tiles per block
#define LDX 66         // padded leading dim for x tile  [128][66]
#define LDL 66         // padded leading dim for logits  [64][66]
#define EPSV 1e-12f

typedef unsigned long long u64;

// ---- packed f32x2 helpers (Blackwell FFMA2 path) --------------------------
__device__ __forceinline__ u64 pk2(float lo, float hi) {
    u64 r; asm("mov.b64 %0, {%1, %2};" : "=l"(r) : "f"(lo), "f"(hi)); return r;
}
__device__ __forceinline__ float2 up2(u64 v) {
    float2 f; asm("mov.b64 {%0, %1}, %2;" : "=f"(f.x), "=f"(f.y) : "l"(v)); return f;
}
__device__ __forceinline__ u64 fma2_(u64 a, u64 b, u64 c) {
    u64 d; asm("fma.rn.f32x2 %0, %1, %2, %3;" : "=l"(d) : "l"(a), "l"(b), "l"(c)); return d;
}
__device__ __forceinline__ u64 add2_(u64 a, u64 b) {
    u64 d; asm("add.rn.f32x2 %0, %1, %2;" : "=l"(d) : "l"(a), "l"(b)); return d;
}

// Scratch (allocation-free rule: __device__ globals)
__device__ float g_agg[BB * KK * CC];   // 1 MB
__device__ float g_asum[BB * KK];

// ---------------------------------------------------------------------------
__global__ void zero_scratch() {
    int i = blockIdx.x * blockDim.x + threadIdx.x;
    const int tot = BB * KK * CC + BB * KK;
    for (; i < tot; i += gridDim.x * blockDim.x) {
        if (i < BB * KK * CC) g_agg[i] = 0.0f;
        else g_asum[i - BB * KK * CC] = 0.0f;
    }
}

// ---------------------------------------------------------------------------
// Fused: logits GEMM -> relu+softmax(K) -> aggregation GEMM (+ a row-sums)
// grid (SPLITS, BB), 256 threads
__global__ __launch_bounds__(256, 2) void netvlad_main(
    const float* __restrict__ x,
    const float* __restrict__ conv_w,
    const float* __restrict__ conv_b)
{
    extern __shared__ float smem[];
    float* sW = smem;                       // [64][128]   8192
    float* sB = sW + KK * CC;               // [64]          64
    float* sX = sB + KK;                    // [128][66]   8448
    float* sL = sX + CC * LDX;              // [64][66]    4224

    const int b     = blockIdx.y;
    const int split = blockIdx.x;
    const int t     = threadIdx.x;

    // Load conv_w / conv_b once
    for (int i = t; i < KK * CC; i += 256) sW[i] = conv_w[i];
    if (t < KK) sB[t] = conv_b[t];

    // Phase-1 mapping: 4k x 4n per thread
    const int ng1 = t & 15;        // n = ng1*4 + j
    const int kq1 = t >> 4;        // k = kq1*4 + i
    // Softmax mapping: 4 sub-threads per column
    const int col = t >> 2;
    const int sub = t & 3;
    // Phase-3 mapping: 4k x 8c per thread (c strided by 16 -> conflict-free)
    const int cg  = t & 15;        // c = cg + 16*j
    const int kq3 = t >> 4;        // k = kq3*4 + i

    // Packed accumulators: lo lane = even-n partial, hi lane = odd-n partial
    u64 vacc2[4][8];
    #pragma unroll
    for (int i = 0; i < 4; i++)
        #pragma unroll
        for (int j = 0; j < 8; j++) vacc2[i][j] = 0ull;
    u64 sacc2[4] = {0ull, 0ull, 0ull, 0ull};

    const int n_base0 = split * (NN / SPLITS);
    const float* xb = x + (size_t)b * CC * NN;

    __syncthreads();   // sW/sB ready

    for (int tile = 0; tile < TILES; tile++) {
        const int n0 = n_base0 + tile * TN;

        // ---- stage x tile: 128 rows x 64 floats, coalesced float4 ----
        {
            const int row_in = t >> 4;        // 0..15
            const int j4     = (t & 15) * 4;  // 0..60
            #pragma unroll
            for (int p = 0; p < 8; p++) {
                int c = p * 16 + row_in;
                float4 v = *(const float4*)(xb + (size_t)c * NN + n0 + j4);
                float* d = &sX[c * LDX + j4];
                d[0] = v.x; d[1] = v.y; d[2] = v.z; d[3] = v.w;
            }
        }
        __syncthreads();

        // ---- phase 1: logits[k][n] = sum_c w[k][c] * x[c][n]  (FFMA2) ----
        {
            // acc2[i][0] covers (n1, n1+1), acc2[i][1] covers (n1+2, n1+3)
            u64 acc2[4][2];
            #pragma unroll
            for (int i = 0; i < 4; i++) { acc2[i][0] = 0ull; acc2[i][1] = 0ull; }

            const int n1 = ng1 * 4;
            #pragma unroll 4
            for (int c = 0; c < CC; c += 2) {
                u64 xa0 = *(const u64*)&sX[c * LDX + n1];
                u64 xb0 = *(const u64*)&sX[c * LDX + n1 + 2];
                u64 xa1 = *(const u64*)&sX[(c + 1) * LDX + n1];
                u64 xb1 = *(const u64*)&sX[(c + 1) * LDX + n1 + 2];
                #pragma unroll
                for (int i = 0; i < 4; i++) {
                    float2 w2 = *(const float2*)&sW[(kq1 * 4 + i) * CC + c];
                    u64 p0 = pk2(w2.x, w2.x);
                    u64 p1 = pk2(w2.y, w2.y);
                    acc2[i][0] = fma2_(p0, xa0, acc2[i][0]);
                    acc2[i][1] = fma2_(p0, xb0, acc2[i][1]);
                    acc2[i][0] = fma2_(p1, xa1, acc2[i][0]);
                    acc2[i][1] = fma2_(p1, xb1, acc2[i][1]);
                }
            }
            #pragma unroll
            for (int i = 0; i < 4; i++) {
                float bias = sB[kq1 * 4 + i];
                float2 lo = up2(acc2[i][0]);
                float2 hi = up2(acc2[i][1]);
                float* dst = &sL[(kq1 * 4 + i) * LDL + n1];
                dst[0] = lo.x + bias;
                dst[1] = lo.y + bias;
                dst[2] = hi.x + bias;
                dst[3] = hi.y + bias;
            }
        }
        __syncthreads();

        // ---- phase 2: softmax(relu(logits)) over k, per column n ----
        {
            float e[16];
            float m = 0.0f;   // relu => max >= 0
            #pragma unroll
            for (int i = 0; i < 16; i++) {
                float v = sL[(sub + 4 * i) * LDL + col];
                v = fmaxf(v, 0.0f);
                e[i] = v;
                m = fmaxf(m, v);
            }
            m = fmaxf(m, __shfl_xor_sync(0xffffffffu, m, 1));
            m = fmaxf(m, __shfl_xor_sync(0xffffffffu, m, 2));
            float s = 0.0f;
            #pragma unroll
            for (int i = 0; i < 16; i++) {
                e[i] = __expf(e[i] - m);
                s += e[i];
            }
            s += __shfl_xor_sync(0xffffffffu, s, 1);
            s += __shfl_xor_sync(0xffffffffu, s, 2);
            float inv = 1.0f / s;
            #pragma unroll
            for (int i = 0; i < 16; i++)
                sL[(sub + 4 * i) * LDL + col] = e[i] * inv;
        }
        __syncthreads();

        // ---- phase 3: vacc[k][c] += sum_n a[k][n]*x[c][n]  (FFMA2, lo/hi
        //      lanes hold even/odd-n partial sums) ----
        {
            #pragma unroll 2
            for (int n = 0; n < TN; n += 2) {
                u64 a2[4];
                #pragma unroll
                for (int i = 0; i < 4; i++)
                    a2[i] = *(const u64*)&sL[(kq3 * 4 + i) * LDL + n];
                u64 x2[8];
                #pragma unroll
                for (int j = 0; j < 8; j++)
                    x2[j] = *(const u64*)&sX[(cg + 16 * j) * LDX + n];
                #pragma unroll
                for (int i = 0; i < 4; i++)
                    #pragma unroll
                    for (int j = 0; j < 8; j++)
                        vacc2[i][j] = fma2_(a2[i], x2[j], vacc2[i][j]);
                if (cg == 0) {
                    #pragma unroll
                    for (int i = 0; i < 4; i++)
                        sacc2[i] = add2_(sacc2[i], a2[i]);
                }
            }
        }
        __syncthreads();
    }

    // ---- accumulate partials to global ----
    float* agg = g_agg + (size_t)b * KK * CC;
    #pragma unroll
    for (int i = 0; i < 4; i++) {
        int k = kq3 * 4 + i;
        #pragma unroll
        for (int j = 0; j < 8; j++) {
            int c = cg + 16 * j;
            float2 f = up2(vacc2[i][j]);
            atomicAdd(&agg[k * CC + c], f.x + f.y);
        }
    }
    if (cg == 0) {
        #pragma unroll
        for (int i = 0; i < 4; i++) {
            float2 f = up2(sacc2[i]);
            atomicAdd(&g_asum[b * KK + kq3 * 4 + i], f.x + f.y);
        }
    }
}

// ---------------------------------------------------------------------------
// Finalize: residual vs centroids, intra-norm (over C), global norm (over K*C)
// grid (BB), 256 threads (8 warps, each warp: 8 rows)
__global__ __launch_bounds__(256) void netvlad_finalize(
    const float* __restrict__ centroids,
    float* __restrict__ out)
{
    __shared__ float sred[8];
    const int b = blockIdx.x;
    const int t = threadIdx.x;
    const int lane = t & 31;
    const int w = t >> 5;

    const float* agg = g_agg + (size_t)b * KK * CC;
    const float* as  = g_asum + b * KK;

    float v[8][4];
    float gss = 0.0f;

    #pragma unroll
    for (int r = 0; r < 8; r++) {
        const int k = w * 8 + r;
        const float s = as[k];
        const int c4 = lane * 4;
        float4 a = *(const float4*)&agg[k * CC + c4];
        float4 cn = *(const float4*)&centroids[k * CC + c4];
        v[r][0] = a.x - s * cn.x;
        v[r][1] = a.y - s * cn.y;
        v[r][2] = a.z - s * cn.z;
        v[r][3] = a.w - s * cn.w;
        float ss = v[r][0]*v[r][0] + v[r][1]*v[r][1] + v[r][2]*v[r][2] + v[r][3]*v[r][3];
        #pragma unroll
        for (int off = 16; off > 0; off >>= 1)
            ss += __shfl_xor_sync(0xffffffffu, ss, off);
        float scale = 1.0f / fmaxf(sqrtf(ss), EPSV);
        #pragma unroll
        for (int j = 0; j < 4; j++) {
            v[r][j] *= scale;
            gss += v[r][j] * v[r][j];
        }
    }

    #pragma unroll
    for (int off = 16; off > 0; off >>= 1)
        gss += __shfl_xor_sync(0xffffffffu, gss, off);
    if (lane == 0) sred[w] = gss;
    __syncthreads();
    float tot = 0.0f;
    #pragma unroll
    for (int i = 0; i < 8; i++) tot += sred[i];
    float gscale = 1.0f / fmaxf(sqrtf(tot), EPSV);

    #pragma unroll
    for (int r = 0; r < 8; r++) {
        const int k = w * 8 + r;
        float4 o;
        o.x = v[r][0] * gscale;
        o.y = v[r][1] * gscale;
        o.z = v[r][2] * gscale;
        o.w = v[r][3] * gscale;
        *(float4*)&out[(size_t)b * KK * CC + k * CC + lane * 4] = o;
    }
}

// ---------------------------------------------------------------------------
extern "C" void kernel_launch(void* const* d_in, const int* in_sizes, int n_in,
                              void* d_out, int out_size)
{
    const float* x         = (const float*)d_in[0];
    const float* conv_w    = (const float*)d_in[1];
    const float* conv_b    = (const float*)d_in[2];
    const float* centroids = (const float*)d_in[3];
    float* out = (float*)d_out;

    const int smem_bytes = (KK * CC + KK + CC * LDX + KK * LDL) * (int)sizeof(float);
    static bool attr_set = false;
    if (!attr_set) {
        cudaFuncSetAttribute(netvlad_main,
                             cudaFuncAttributeMaxDynamicSharedMemorySize,
                             smem_bytes);
        attr_set = true;
    }

    zero_scratch<<<264, 1024>>>();
    dim3 grid(SPLITS, BB);
    netvlad_main<<<grid, 256, smem_bytes>>>(x, conv_w, conv_b);
    netvlad_finalize<<<BB, 256>>>(centroids, out);
}

// round 7
// speedup vs baseline: 1.4540x; 1.4538x over previous
#include <cuda_runtime.h>
#include <cstdint>

#define BB 32
#define CC 128
#define NN 16384
#define KK 64
#define TN 64
#define SPLITS 32
#define TILES ((NN / SPLITS) / TN)   // 8 tiles per CTA
#define EPSV 1e-12f

// ---- SMEM layout (float offsets) ----
#define WSTR  132
#define XTSTR 132
#define XSTR  68
#define ASTR  68
#define F_WH  0
#define F_WL  (F_WH  + 64 * WSTR)
#define F_XTH (F_WL  + 64 * WSTR)
#define F_XTL (F_XTH + 64 * XTSTR)
#define F_XH  (F_XTL + 64 * XTSTR)
#define F_A0  (F_XH  + 128 * XSTR)   // D1 partial (c 0-63)  / later a_hi
#define F_A1  (F_A0  + 64 * ASTR)    // D1 partial (c 64-127)/ later a_lo
#define SMEM_FLOATS (F_A1 + 64 * ASTR)   // 51200 floats = 204800 B

__device__ __forceinline__ float to_tf32(float v) {
    uint32_t r; asm("cvt.rna.tf32.f32 %0, %1;" : "=r"(r) : "f"(v));
    return __uint_as_float(r);
}

__device__ __forceinline__ void mma_tf32(float d[4], const uint32_t a[4],
                                         uint32_t b0, uint32_t b1) {
    asm volatile(
        "mma.sync.aligned.m16n8k8.row.col.f32.tf32.tf32.f32 "
        "{%0,%1,%2,%3},{%4,%5,%6,%7},{%8,%9},{%0,%1,%2,%3};"
        : "+f"(d[0]), "+f"(d[1]), "+f"(d[2]), "+f"(d[3])
        : "r"(a[0]), "r"(a[1]), "r"(a[2]), "r"(a[3]), "r"(b0), "r"(b1));
}

// ---- scratch ----
__device__ float g_agg[BB * KK * CC];
__device__ float g_asum[BB * KK];

__global__ void zero_scratch() {
    int i = blockIdx.x * blockDim.x + threadIdx.x;
    const int tot = BB * KK * CC + BB * KK;
    for (; i < tot; i += gridDim.x * blockDim.x) {
        if (i < BB * KK * CC) g_agg[i] = 0.0f;
        else g_asum[i - BB * KK * CC] = 0.0f;
    }
}

// ---------------------------------------------------------------------------
__global__ __launch_bounds__(256, 1) void netvlad_main(
    const float* __restrict__ x,
    const float* __restrict__ conv_w,
    const float* __restrict__ conv_b)
{
    extern __shared__ float sm[];
    float* sWh  = sm + F_WH;
    float* sWl  = sm + F_WL;
    float* sXTh = sm + F_XTH;
    float* sXTl = sm + F_XTL;
    float* sXh  = sm + F_XH;
    float* sA0  = sm + F_A0;
    float* sA1  = sm + F_A1;

    const int t = threadIdx.x;
    const int wid = t >> 5;
    const int lane = t & 31;
    const int g = lane >> 2;      // fragment group
    const int tig = lane & 3;     // thread-in-group
    const int b = blockIdx.y;
    const int split = blockIdx.x;

    // phase-1 warp mapping: cgrp = c-half, 2x2 warps over (n,k) 32x32 tiles
    const int cgrp = wid >> 2;
    const int nb1 = (wid & 1) * 32;
    const int kb1 = ((wid >> 1) & 1) * 32;
    // phase-3 warp mapping: 2(k) x 4(c) warps, 32x32 tiles
    const int kb3 = (wid >> 2) * 32;
    const int cb3 = (wid & 3) * 32;
    // softmax mapping
    const int sn = t >> 2;
    const int sub = t & 3;

    // ---- stage W (hi/lo) ----
    {
        const int k = t >> 2;
        const int c0 = (t & 3) * 4;
        #pragma unroll
        for (int p = 0; p < 8; p++) {
            int c = c0 + 16 * p;
            float4 v = *(const float4*)(conv_w + k * CC + c);
            float4 h, l;
            h.x = to_tf32(v.x); h.y = to_tf32(v.y); h.z = to_tf32(v.z); h.w = to_tf32(v.w);
            l.x = to_tf32(v.x - h.x); l.y = to_tf32(v.y - h.y);
            l.z = to_tf32(v.z - h.z); l.w = to_tf32(v.w - h.w);
            *(float4*)&sWh[k * WSTR + c] = h;
            *(float4*)&sWl[k * WSTR + c] = l;
        }
    }

    float biasr[16];
    #pragma unroll
    for (int i = 0; i < 16; i++) biasr[i] = conv_b[sub + 4 * i];

    float asum_part[16];
    #pragma unroll
    for (int i = 0; i < 16; i++) asum_part[i] = 0.0f;

    float d3[2][4][4];
    #pragma unroll
    for (int mf = 0; mf < 2; mf++)
        #pragma unroll
        for (int nf = 0; nf < 4; nf++)
            #pragma unroll
            for (int q = 0; q < 4; q++) d3[mf][nf][q] = 0.0f;

    const float* xb = x + (size_t)b * CC * NN;
    const int n_base = split * (NN / SPLITS);

    __syncthreads();

    for (int tile = 0; tile < TILES; tile++) {
        const int n0 = n_base + tile * TN;

        // ---- stage x tile: x_hi [c][68], xT_hi/lo [n][132] ----
        {
            const int cs = t >> 4;          // 0..15
            const int nf4 = (t & 15) * 4;   // 0..60
            #pragma unroll
            for (int p = 0; p < 8; p++) {
                int c = cs + 16 * p;
                float4 v = *(const float4*)(xb + (size_t)c * NN + n0 + nf4);
                float4 h, l;
                h.x = to_tf32(v.x); h.y = to_tf32(v.y); h.z = to_tf32(v.z); h.w = to_tf32(v.w);
                l.x = to_tf32(v.x - h.x); l.y = to_tf32(v.y - h.y);
                l.z = to_tf32(v.z - h.z); l.w = to_tf32(v.w - h.w);
                *(float4*)&sXh[c * XSTR + nf4] = h;
                sXTh[(nf4 + 0) * XTSTR + c] = h.x;
                sXTh[(nf4 + 1) * XTSTR + c] = h.y;
                sXTh[(nf4 + 2) * XTSTR + c] = h.z;
                sXTh[(nf4 + 3) * XTSTR + c] = h.w;
                sXTl[(nf4 + 0) * XTSTR + c] = l.x;
                sXTl[(nf4 + 1) * XTSTR + c] = l.y;
                sXTl[(nf4 + 2) * XTSTR + c] = l.z;
                sXTl[(nf4 + 3) * XTSTR + c] = l.w;
            }
        }
        __syncthreads();

        // ---- phase 1: D1[n][k] = xT @ W^T over c-half, 3-pass tf32 split ----
        {
            float d1[2][4][4];
            #pragma unroll
            for (int mf = 0; mf < 2; mf++)
                #pragma unroll
                for (int nf = 0; nf < 4; nf++)
                    #pragma unroll
                    for (int q = 0; q < 4; q++) d1[mf][nf][q] = 0.0f;

            #pragma unroll
            for (int pass = 0; pass < 3; pass++) {
                const float* Am = (pass == 1) ? sXTl : sXTh;
                const float* Bm = (pass == 2) ? sWl : sWh;
                #pragma unroll
                for (int s = 0; s < 8; s++) {
                    const int c8 = cgrp * 64 + s * 8 + tig;
                    uint32_t af[2][4];
                    #pragma unroll
                    for (int mf = 0; mf < 2; mf++) {
                        const float* p = Am + (nb1 + mf * 16 + g) * XTSTR + c8;
                        af[mf][0] = __float_as_uint(p[0]);
                        af[mf][1] = __float_as_uint(p[8 * XTSTR]);
                        af[mf][2] = __float_as_uint(p[4]);
                        af[mf][3] = __float_as_uint(p[8 * XTSTR + 4]);
                    }
                    #pragma unroll
                    for (int nf = 0; nf < 4; nf++) {
                        const float* q = Bm + (kb1 + nf * 8 + g) * WSTR + c8;
                        uint32_t b0 = __float_as_uint(q[0]);
                        uint32_t b1 = __float_as_uint(q[4]);
                        mma_tf32(d1[0][nf], af[0], b0, b1);
                        mma_tf32(d1[1][nf], af[1], b0, b1);
                    }
                }
            }
            // store partial logits (no bias) to sA0/sA1 (per c-half)
            float* sLd = cgrp ? sA1 : sA0;
            #pragma unroll
            for (int mf = 0; mf < 2; mf++) {
                #pragma unroll
                for (int nf = 0; nf < 4; nf++) {
                    int r0 = nb1 + mf * 16 + g;
                    int cl = kb1 + nf * 8 + 2 * tig;
                    *(float2*)&sLd[r0 * ASTR + cl] =
                        make_float2(d1[mf][nf][0], d1[mf][nf][1]);
                    *(float2*)&sLd[(r0 + 8) * ASTR + cl] =
                        make_float2(d1[mf][nf][2], d1[mf][nf][3]);
                }
            }
        }
        __syncthreads();

        // ---- softmax(relu(logits)) over k, per column n ----
        float av[16];
        {
            float m = 0.0f;
            #pragma unroll
            for (int i = 0; i < 16; i++) {
                int k = sub + 4 * i;
                float v = sA0[sn * ASTR + k] + sA1[sn * ASTR + k] + biasr[i];
                v = fmaxf(v, 0.0f);
                av[i] = v;
                m = fmaxf(m, v);
            }
            m = fmaxf(m, __shfl_xor_sync(0xffffffffu, m, 1));
            m = fmaxf(m, __shfl_xor_sync(0xffffffffu, m, 2));
            float s = 0.0f;
            #pragma unroll
            for (int i = 0; i < 16; i++) { av[i] = __expf(av[i] - m); s += av[i]; }
            s += __shfl_xor_sync(0xffffffffu, s, 1);
            s += __shfl_xor_sync(0xffffffffu, s, 2);
            float inv = 1.0f / s;
            #pragma unroll
            for (int i = 0; i < 16; i++) {
                av[i] *= inv;
                asum_part[i] += av[i];
            }
        }
        __syncthreads();   // all logits reads done before aliasing writes

        // write a_hi (sA0) / a_lo (sA1) in [k][68] layout
        #pragma unroll
        for (int i = 0; i < 16; i++) {
            int k = sub + 4 * i;
            float ah = to_tf32(av[i]);
            float al = to_tf32(av[i] - ah);
            sA0[k * ASTR + sn] = ah;
            sA1[k * ASTR + sn] = al;
        }
        __syncthreads();

        // ---- phase 3: D3[k][c] += a @ x^T  (x_hi only; a_hi + a_lo) ----
        #pragma unroll
        for (int pass = 0; pass < 2; pass++) {
            const float* Ap = pass ? sA1 : sA0;
            #pragma unroll
            for (int s = 0; s < 8; s++) {
                const int n8 = s * 8 + tig;
                uint32_t af[2][4];
                #pragma unroll
                for (int mf = 0; mf < 2; mf++) {
                    const float* p = Ap + (kb3 + mf * 16 + g) * ASTR + n8;
                    af[mf][0] = __float_as_uint(p[0]);
                    af[mf][1] = __float_as_uint(p[8 * ASTR]);
                    af[mf][2] = __float_as_uint(p[4]);
                    af[mf][3] = __float_as_uint(p[8 * ASTR + 4]);
                }
                #pragma unroll
                for (int nf = 0; nf < 4; nf++) {
                    const float* q = sXh + (cb3 + nf * 8 + g) * XSTR + n8;
                    uint32_t b0 = __float_as_uint(q[0]);
                    uint32_t b1 = __float_as_uint(q[4]);
                    mma_tf32(d3[0][nf], af[0], b0, b1);
                    mma_tf32(d3[1][nf], af[1], b0, b1);
                }
            }
        }
        __syncthreads();   // a/x buffers free for next tile
    }

    // ---- commit D3 to global ----
    float* agg = g_agg + (size_t)b * KK * CC;
    #pragma unroll
    for (int mf = 0; mf < 2; mf++) {
        #pragma unroll
        for (int nf = 0; nf < 4; nf++) {
            int k0 = kb3 + mf * 16 + g;
            int c0 = cb3 + nf * 8 + 2 * tig;
            atomicAdd(&agg[k0 * CC + c0],       d3[mf][nf][0]);
            atomicAdd(&agg[k0 * CC + c0 + 1],   d3[mf][nf][1]);
            atomicAdd(&agg[(k0 + 8) * CC + c0],     d3[mf][nf][2]);
            atomicAdd(&agg[(k0 + 8) * CC + c0 + 1], d3[mf][nf][3]);
        }
    }
    // asum: reduce lanes sharing `sub` within warp, commit from lanes 0-3
    #pragma unroll
    for (int i = 0; i < 16; i++) {
        float v = asum_part[i];
        v += __shfl_xor_sync(0xffffffffu, v, 4);
        v += __shfl_xor_sync(0xffffffffu, v, 8);
        v += __shfl_xor_sync(0xffffffffu, v, 16);
        if (lane < 4)
            atomicAdd(&g_asum[b * KK + sub + 4 * i], v);
    }
}

// ---------------------------------------------------------------------------
__global__ __launch_bounds__(256) void netvlad_finalize(
    const float* __restrict__ centroids,
    float* __restrict__ out)
{
    __shared__ float sred[8];
    const int b = blockIdx.x;
    const int t = threadIdx.x;
    const int lane = t & 31;
    const int w = t >> 5;

    const float* agg = g_agg + (size_t)b * KK * CC;
    const float* as  = g_asum + b * KK;

    float v[8][4];
    float gss = 0.0f;

    #pragma unroll
    for (int r = 0; r < 8; r++) {
        const int k = w * 8 + r;
        const float s = as[k];
        const int c4 = lane * 4;
        float4 a = *(const float4*)&agg[k * CC + c4];
        float4 cn = *(const float4*)&centroids[k * CC + c4];
        v[r][0] = a.x - s * cn.x;
        v[r][1] = a.y - s * cn.y;
        v[r][2] = a.z - s * cn.z;
        v[r][3] = a.w - s * cn.w;
        float ss = v[r][0]*v[r][0] + v[r][1]*v[r][1] + v[r][2]*v[r][2] + v[r][3]*v[r][3];
        #pragma unroll
        for (int off = 16; off > 0; off >>= 1)
            ss += __shfl_xor_sync(0xffffffffu, ss, off);
        float scale = 1.0f / fmaxf(sqrtf(ss), EPSV);
        #pragma unroll
        for (int j = 0; j < 4; j++) { v[r][j] *= scale; gss += v[r][j] * v[r][j]; }
    }

    #pragma unroll
    for (int off = 16; off > 0; off >>= 1)
        gss += __shfl_xor_sync(0xffffffffu, gss, off);
    if (lane == 0) sred[w] = gss;
    __syncthreads();
    float tot = 0.0f;
    #pragma unroll
    for (int i = 0; i < 8; i++) tot += sred[i];
    float gscale = 1.0f / fmaxf(sqrtf(tot), EPSV);

    #pragma unroll
    for (int r = 0; r < 8; r++) {
        const int k = w * 8 + r;
        float4 o;
        o.x = v[r][0] * gscale; o.y = v[r][1] * gscale;
        o.z = v[r][2] * gscale; o.w = v[r][3] * gscale;
        *(float4*)&out[(size_t)b * KK * CC + k * CC + lane * 4] = o;
    }
}

// ---------------------------------------------------------------------------
extern "C" void kernel_launch(void* const* d_in, const int* in_sizes, int n_in,
                              void* d_out, int out_size)
{
    const float* x         = (const float*)d_in[0];
    const float* conv_w    = (const float*)d_in[1];
    const float* conv_b    = (const float*)d_in[2];
    const float* centroids = (const float*)d_in[3];
    float* out = (float*)d_out;

    const int smem_bytes = SMEM_FLOATS * (int)sizeof(float);   // 204800
    static bool attr_set = false;
    if (!attr_set) {
        cudaFuncSetAttribute(netvlad_main,
                             cudaFuncAttributeMaxDynamicSharedMemorySize,
                             smem_bytes);
        attr_set = true;
    }

    zero_scratch<<<264, 1024>>>();
    dim3 grid(SPLITS, BB);
    netvlad_main<<<grid, 256, smem_bytes>>>(x, conv_w, conv_b);
    netvlad_finalize<<<BB, 256>>>(centroids, out);
}

// round 8
// speedup vs baseline: 2.2558x; 1.5514x over previous
#include <cuda_runtime.h>
#include <cuda_bf16.h>
#include <cstdint>

#define BB 32
#define CC 128
#define NN 16384
#define KK 64
#define TN 64
#define SPLITS 32
#define TILES ((NN / SPLITS) / TN)   // 8 tiles per CTA
#define EPSV 1e-12f

// ---- SMEM layout (uint32 units) ----
#define WSTR   68     // W pairs [k=64][cp=64], stride 68 (mod32=4)
#define XCSTR  72     // x c-paired [cp=64][n=64], stride 72 (mod32=8)
#define XNSTR  36     // x n-paired [c=128][np=32], stride 36 (mod32=4)
#define AST32  36     // a n-paired [k=64][np=32]
#define LDL    68     // logits float [n=64][k], stride 68
#define U_WH   0
#define U_WL   (U_WH  + 64 * WSTR)
#define U_XCH  (U_WL  + 64 * WSTR)
#define U_XCL  (U_XCH + 64 * XCSTR)
#define U_XNH  (U_XCL + 64 * XCSTR)
#define U_XNL  (U_XNH + 128 * XNSTR)
#define U_L0   (U_XNL + 128 * XNSTR)
#define U_L1   (U_L0  + 64 * LDL)
#define U_AH   U_L0          // aliased (sync-separated)
#define U_AL   U_L1
#define SMEM_U32 (U_L1 + 64 * LDL)   // 35840 u32 = 143360 B

__device__ __forceinline__ uint32_t pkbf(float lo, float hi) {
    unsigned short a = __bfloat16_as_ushort(__float2bfloat16_rn(lo));
    unsigned short b = __bfloat16_as_ushort(__float2bfloat16_rn(hi));
    return (uint32_t)a | ((uint32_t)b << 16);
}
__device__ __forceinline__ void bsplit(float x, float& h, float& l) {
    __nv_bfloat16 hb = __float2bfloat16_rn(x);
    h = __bfloat162float(hb);
    l = x - h;   // bf16-rounded when packed
}

__device__ __forceinline__ void mma_bf16(float d[4], const uint32_t a[4],
                                         uint32_t b0, uint32_t b1) {
    asm volatile(
        "mma.sync.aligned.m16n8k16.row.col.f32.bf16.bf16.f32 "
        "{%0,%1,%2,%3},{%4,%5,%6,%7},{%8,%9},{%0,%1,%2,%3};"
        : "+f"(d[0]), "+f"(d[1]), "+f"(d[2]), "+f"(d[3])
        : "r"(a[0]), "r"(a[1]), "r"(a[2]), "r"(a[3]), "r"(b0), "r"(b1));
}

// ---- scratch ----
__device__ float g_agg[BB * KK * CC];
__device__ float g_asum[BB * KK];

__global__ void zero_scratch() {
    int i = blockIdx.x * blockDim.x + threadIdx.x;
    const int tot = BB * KK * CC + BB * KK;
    for (; i < tot; i += gridDim.x * blockDim.x) {
        if (i < BB * KK * CC) g_agg[i] = 0.0f;
        else g_asum[i - BB * KK * CC] = 0.0f;
    }
}

// ---------------------------------------------------------------------------
__global__ __launch_bounds__(256, 1) void netvlad_main(
    const float* __restrict__ x,
    const float* __restrict__ conv_w,
    const float* __restrict__ conv_b)
{
    extern __shared__ uint32_t smu[];

    const int t = threadIdx.x;
    const int wid = t >> 5;
    const int lane = t & 31;
    const int g = lane >> 2;
    const int tig = lane & 3;
    const int b = blockIdx.y;
    const int split = blockIdx.x;

    // phase-1: warp tile 32k x 32n, cgrp halves contraction c
    const int cgrp = wid >> 2;
    const int kb1 = (wid & 1) * 32;
    const int nb1 = ((wid >> 1) & 1) * 32;
    // phase-3: warp tile 32k x 32c, full n contraction
    const int kb3 = (wid >> 2) * 32;
    const int cb3 = (wid & 3) * 32;
    // softmax mapping
    const int sn = t >> 2;
    const int sub = t & 3;

    // ---- stage W (hi/lo bf16, c-paired) ----
    {
        const int k = t >> 2;
        const int c8 = (t & 3) * 8;
        #pragma unroll
        for (int p = 0; p < 4; p++) {
            int c = c8 + 32 * p;
            float4 va = *(const float4*)(conv_w + k * CC + c);
            float4 vb = *(const float4*)(conv_w + k * CC + c + 4);
            float h[8], l[8];
            bsplit(va.x, h[0], l[0]); bsplit(va.y, h[1], l[1]);
            bsplit(va.z, h[2], l[2]); bsplit(va.w, h[3], l[3]);
            bsplit(vb.x, h[4], l[4]); bsplit(vb.y, h[5], l[5]);
            bsplit(vb.z, h[6], l[6]); bsplit(vb.w, h[7], l[7]);
            uint4 uh = make_uint4(pkbf(h[0], h[1]), pkbf(h[2], h[3]),
                                  pkbf(h[4], h[5]), pkbf(h[6], h[7]));
            uint4 ul = make_uint4(pkbf(l[0], l[1]), pkbf(l[2], l[3]),
                                  pkbf(l[4], l[5]), pkbf(l[6], l[7]));
            *(uint4*)&smu[U_WH + k * WSTR + c / 2] = uh;
            *(uint4*)&smu[U_WL + k * WSTR + c / 2] = ul;
        }
    }

    float biasr[16];
    #pragma unroll
    for (int i = 0; i < 16; i++) biasr[i] = conv_b[sub + 4 * i];

    float asum_part[16];
    #pragma unroll
    for (int i = 0; i < 16; i++) asum_part[i] = 0.0f;

    float d3[2][4][4];
    #pragma unroll
    for (int mf = 0; mf < 2; mf++)
        #pragma unroll
        for (int nf = 0; nf < 4; nf++)
            #pragma unroll
            for (int q = 0; q < 4; q++) d3[mf][nf][q] = 0.0f;

    const float* xb = x + (size_t)b * CC * NN;
    const int n_base = split * (NN / SPLITS);

    __syncthreads();

    for (int tile = 0; tile < TILES; tile++) {
        const int n0 = n_base + tile * TN;

        // ---- stage x tile: c-paired (for P1-B) and n-paired (for P3-B) ----
        {
            const int q0 = t >> 4;           // cpair 0..15
            const int i4 = (t & 15) * 4;     // n offset
            #pragma unroll
            for (int p = 0; p < 4; p++) {
                int cp = q0 + 16 * p;
                float4 v0 = *(const float4*)(xb + (size_t)(2 * cp) * NN + n0 + i4);
                float4 v1 = *(const float4*)(xb + (size_t)(2 * cp + 1) * NN + n0 + i4);
                float h0[4], l0[4], h1[4], l1[4];
                bsplit(v0.x, h0[0], l0[0]); bsplit(v0.y, h0[1], l0[1]);
                bsplit(v0.z, h0[2], l0[2]); bsplit(v0.w, h0[3], l0[3]);
                bsplit(v1.x, h1[0], l1[0]); bsplit(v1.y, h1[1], l1[1]);
                bsplit(v1.z, h1[2], l1[2]); bsplit(v1.w, h1[3], l1[3]);
                // c-paired: word = (even-c, odd-c) at each n
                uint4 ch = make_uint4(pkbf(h0[0], h1[0]), pkbf(h0[1], h1[1]),
                                      pkbf(h0[2], h1[2]), pkbf(h0[3], h1[3]));
                uint4 cl = make_uint4(pkbf(l0[0], l1[0]), pkbf(l0[1], l1[1]),
                                      pkbf(l0[2], l1[2]), pkbf(l0[3], l1[3]));
                *(uint4*)&smu[U_XCH + cp * XCSTR + i4] = ch;
                *(uint4*)&smu[U_XCL + cp * XCSTR + i4] = cl;
                // n-paired: per c row, word = (even-n, odd-n)
                uint2 nh0 = make_uint2(pkbf(h0[0], h0[1]), pkbf(h0[2], h0[3]));
                uint2 nh1 = make_uint2(pkbf(h1[0], h1[1]), pkbf(h1[2], h1[3]));
                uint2 nl0 = make_uint2(pkbf(l0[0], l0[1]), pkbf(l0[2], l0[3]));
                uint2 nl1 = make_uint2(pkbf(l1[0], l1[1]), pkbf(l1[2], l1[3]));
                *(uint2*)&smu[U_XNH + (2 * cp) * XNSTR + i4 / 2] = nh0;
                *(uint2*)&smu[U_XNH + (2 * cp + 1) * XNSTR + i4 / 2] = nh1;
                *(uint2*)&smu[U_XNL + (2 * cp) * XNSTR + i4 / 2] = nl0;
                *(uint2*)&smu[U_XNL + (2 * cp + 1) * XNSTR + i4 / 2] = nl1;
            }
        }
        __syncthreads();

        // ---- phase 1: D1[k][n] = W @ x over c-half, 3-pass bf16 split ----
        {
            float d1[2][4][4];
            #pragma unroll
            for (int mf = 0; mf < 2; mf++)
                #pragma unroll
                for (int nf = 0; nf < 4; nf++)
                    #pragma unroll
                    for (int q = 0; q < 4; q++) d1[mf][nf][q] = 0.0f;

            #pragma unroll
            for (int pass = 0; pass < 3; pass++) {
                const uint32_t Ab = (pass == 2) ? U_WL : U_WH;
                const uint32_t Bb = (pass == 1) ? U_XCL : U_XCH;
                #pragma unroll
                for (int s = 0; s < 4; s++) {
                    const int cp0 = cgrp * 32 + s * 8;
                    uint32_t af[2][4];
                    #pragma unroll
                    for (int mf = 0; mf < 2; mf++) {
                        int row = kb1 + mf * 16 + g;
                        af[mf][0] = smu[Ab + row * WSTR + cp0 + tig];
                        af[mf][1] = smu[Ab + (row + 8) * WSTR + cp0 + tig];
                        af[mf][2] = smu[Ab + row * WSTR + cp0 + 4 + tig];
                        af[mf][3] = smu[Ab + (row + 8) * WSTR + cp0 + 4 + tig];
                    }
                    #pragma unroll
                    for (int nf = 0; nf < 4; nf++) {
                        int col = nb1 + nf * 8 + g;
                        uint32_t b0 = smu[Bb + (cp0 + tig) * XCSTR + col];
                        uint32_t b1 = smu[Bb + (cp0 + 4 + tig) * XCSTR + col];
                        mma_bf16(d1[0][nf], af[0], b0, b1);
                        mma_bf16(d1[1][nf], af[1], b0, b1);
                    }
                }
            }
            // store D1 to logits buffer [n][k] for this c-half
            float* sL = (float*)&smu[cgrp ? U_L1 : U_L0];
            #pragma unroll
            for (int mf = 0; mf < 2; mf++) {
                #pragma unroll
                for (int nf = 0; nf < 4; nf++) {
                    int kk = kb1 + mf * 16 + g;
                    int nn = nb1 + nf * 8 + 2 * tig;
                    sL[nn * LDL + kk]           = d1[mf][nf][0];
                    sL[(nn + 1) * LDL + kk]     = d1[mf][nf][1];
                    sL[nn * LDL + kk + 8]       = d1[mf][nf][2];
                    sL[(nn + 1) * LDL + kk + 8] = d1[mf][nf][3];
                }
            }
        }
        __syncthreads();

        // ---- softmax(relu(logits)) over k per column n ----
        float av[16];
        {
            const float* sL0 = (const float*)&smu[U_L0];
            const float* sL1 = (const float*)&smu[U_L1];
            float m = 0.0f;
            #pragma unroll
            for (int i = 0; i < 16; i++) {
                int k = sub + 4 * i;
                float v = sL0[sn * LDL + k] + sL1[sn * LDL + k] + biasr[i];
                v = fmaxf(v, 0.0f);
                av[i] = v;
                m = fmaxf(m, v);
            }
            m = fmaxf(m, __shfl_xor_sync(0xffffffffu, m, 1));
            m = fmaxf(m, __shfl_xor_sync(0xffffffffu, m, 2));
            float s = 0.0f;
            #pragma unroll
            for (int i = 0; i < 16; i++) { av[i] = __expf(av[i] - m); s += av[i]; }
            s += __shfl_xor_sync(0xffffffffu, s, 1);
            s += __shfl_xor_sync(0xffffffffu, s, 2);
            float inv = 1.0f / s;
            #pragma unroll
            for (int i = 0; i < 16; i++) {
                av[i] *= inv;
                asum_part[i] += av[i];
            }
        }
        __syncthreads();   // logits reads done before aliasing a-writes

        // ---- write a hi/lo bf16, n-paired [k][np] (u16 stores) ----
        {
            unsigned short* aH = (unsigned short*)&smu[U_AH];
            unsigned short* aL = (unsigned short*)&smu[U_AL];
            #pragma unroll
            for (int i = 0; i < 16; i++) {
                int k = sub + 4 * i;
                __nv_bfloat16 hb = __float2bfloat16_rn(av[i]);
                float hf = __bfloat162float(hb);
                __nv_bfloat16 lb = __float2bfloat16_rn(av[i] - hf);
                aH[k * (2 * AST32) + sn] = __bfloat16_as_ushort(hb);
                aL[k * (2 * AST32) + sn] = __bfloat16_as_ushort(lb);
            }
        }
        __syncthreads();

        // ---- phase 3: D3[k][c] += a @ x^T, 3-pass bf16 split ----
        #pragma unroll
        for (int pass = 0; pass < 3; pass++) {
            const uint32_t Ab = (pass == 1) ? U_AL : U_AH;
            const uint32_t Bb = (pass == 2) ? U_XNL : U_XNH;
            #pragma unroll
            for (int s = 0; s < 4; s++) {
                const int np0 = s * 8;
                uint32_t af[2][4];
                #pragma unroll
                for (int mf = 0; mf < 2; mf++) {
                    int row = kb3 + mf * 16 + g;
                    af[mf][0] = smu[Ab + row * AST32 + np0 + tig];
                    af[mf][1] = smu[Ab + (row + 8) * AST32 + np0 + tig];
                    af[mf][2] = smu[Ab + row * AST32 + np0 + 4 + tig];
                    af[mf][3] = smu[Ab + (row + 8) * AST32 + np0 + 4 + tig];
                }
                #pragma unroll
                for (int nf = 0; nf < 4; nf++) {
                    int c = cb3 + nf * 8 + g;
                    uint32_t b0 = smu[Bb + c * XNSTR + np0 + tig];
                    uint32_t b1 = smu[Bb + c * XNSTR + np0 + 4 + tig];
                    mma_bf16(d3[0][nf], af[0], b0, b1);
                    mma_bf16(d3[1][nf], af[1], b0, b1);
                }
            }
        }
        __syncthreads();   // x/a buffers free for next tile
    }

    // ---- commit D3 to global ----
    float* agg = g_agg + (size_t)b * KK * CC;
    #pragma unroll
    for (int mf = 0; mf < 2; mf++) {
        #pragma unroll
        for (int nf = 0; nf < 4; nf++) {
            int k0 = kb3 + mf * 16 + g;
            int c0 = cb3 + nf * 8 + 2 * tig;
            atomicAdd(&agg[k0 * CC + c0],           d3[mf][nf][0]);
            atomicAdd(&agg[k0 * CC + c0 + 1],       d3[mf][nf][1]);
            atomicAdd(&agg[(k0 + 8) * CC + c0],     d3[mf][nf][2]);
            atomicAdd(&agg[(k0 + 8) * CC + c0 + 1], d3[mf][nf][3]);
        }
    }
    #pragma unroll
    for (int i = 0; i < 16; i++) {
        float v = asum_part[i];
        v += __shfl_xor_sync(0xffffffffu, v, 4);
        v += __shfl_xor_sync(0xffffffffu, v, 8);
        v += __shfl_xor_sync(0xffffffffu, v, 16);
        if (lane < 4)
            atomicAdd(&g_asum[b * KK + sub + 4 * i], v);
    }
}

// ---------------------------------------------------------------------------
__global__ __launch_bounds__(256) void netvlad_finalize(
    const float* __restrict__ centroids,
    float* __restrict__ out)
{
    __shared__ float sred[8];
    const int b = blockIdx.x;
    const int t = threadIdx.x;
    const int lane = t & 31;
    const int w = t >> 5;

    const float* agg = g_agg + (size_t)b * KK * CC;
    const float* as  = g_asum + b * KK;

    float v[8][4];
    float gss = 0.0f;

    #pragma unroll
    for (int r = 0; r < 8; r++) {
        const int k = w * 8 + r;
        const float s = as[k];
        const int c4 = lane * 4;
        float4 a = *(const float4*)&agg[k * CC + c4];
        float4 cn = *(const float4*)&centroids[k * CC + c4];
        v[r][0] = a.x - s * cn.x;
        v[r][1] = a.y - s * cn.y;
        v[r][2] = a.z - s * cn.z;
        v[r][3] = a.w - s * cn.w;
        float ss = v[r][0]*v[r][0] + v[r][1]*v[r][1] + v[r][2]*v[r][2] + v[r][3]*v[r][3];
        #pragma unroll
        for (int off = 16; off > 0; off >>= 1)
            ss += __shfl_xor_sync(0xffffffffu, ss, off);
        float scale = 1.0f / fmaxf(sqrtf(ss), EPSV);
        #pragma unroll
        for (int j = 0; j < 4; j++) { v[r][j] *= scale; gss += v[r][j] * v[r][j]; }
    }

    #pragma unroll
    for (int off = 16; off > 0; off >>= 1)
        gss += __shfl_xor_sync(0xffffffffu, gss, off);
    if (lane == 0) sred[w] = gss;
    __syncthreads();
    float tot = 0.0f;
    #pragma unroll
    for (int i = 0; i < 8; i++) tot += sred[i];
    float gscale = 1.0f / fmaxf(sqrtf(tot), EPSV);

    #pragma unroll
    for (int r = 0; r < 8; r++) {
        const int k = w * 8 + r;
        float4 o;
        o.x = v[r][0] * gscale; o.y = v[r][1] * gscale;
        o.z = v[r][2] * gscale; o.w = v[r][3] * gscale;
        *(float4*)&out[(size_t)b * KK * CC + k * CC + lane * 4] = o;
    }
}

// ---------------------------------------------------------------------------
extern "C" void kernel_launch(void* const* d_in, const int* in_sizes, int n_in,
                              void* d_out, int out_size)
{
    const float* x         = (const float*)d_in[0];
    const float* conv_w    = (const float*)d_in[1];
    const float* conv_b    = (const float*)d_in[2];
    const float* centroids = (const float*)d_in[3];
    float* out = (float*)d_out;

    const int smem_bytes = SMEM_U32 * 4;   // 143360
    static bool attr_set = false;
    if (!attr_set) {
        cudaFuncSetAttribute(netvlad_main,
                             cudaFuncAttributeMaxDynamicSharedMemorySize,
                             smem_bytes);
        attr_set = true;
    }

    zero_scratch<<<264, 1024>>>();
    dim3 grid(SPLITS, BB);
    netvlad_main<<<grid, 256, smem_bytes>>>(x, conv_w, conv_b);
    netvlad_finalize<<<BB, 256>>>(centroids, out);
}

// round 9
// speedup vs baseline: 2.3085x; 1.0234x over previous
#include <cuda_runtime.h>
#include <cuda_bf16.h>
#include <cstdint>

#define BB 32
#define CC 128
#define NN 16384
#define KK 64
#define TN 64
#define SPLITS 32
#define TILES ((NN / SPLITS) / TN)   // 8 tiles per CTA
#define EPSV 1e-12f

// ---- SMEM layout (uint32 units) ----
#define WSTR   68     // W pairs [k=64][cp=64]
#define XCSTR  72     // x c-paired [cp=64][n=64]
#define XNSTR  36     // x n-paired [c=128][np=32]
#define AST32  36     // a n-paired [k=64][np=32]
#define LDL    68     // logits float [n=64][k]
#define U_WH   0
#define U_WL   (U_WH  + 64 * WSTR)
#define U_XCH  (U_WL  + 64 * WSTR)
#define U_XCL  (U_XCH + 64 * XCSTR)
#define U_XNH  (U_XCL + 64 * XCSTR)
#define U_L0   (U_XNH + 128 * XNSTR)
#define U_L1   (U_L0  + 64 * LDL)
#define U_AH   (U_L1  + 64 * LDL)
#define U_AL   (U_AH  + 64 * AST32)
#define SMEM_U32 (U_AL + 64 * AST32)   // 35840 u32 = 143360 B

__device__ __forceinline__ uint32_t pkbf(float lo, float hi) {
    unsigned short a = __bfloat16_as_ushort(__float2bfloat16_rn(lo));
    unsigned short b = __bfloat16_as_ushort(__float2bfloat16_rn(hi));
    return (uint32_t)a | ((uint32_t)b << 16);
}
__device__ __forceinline__ void bsplit(float x, float& h, float& l) {
    __nv_bfloat16 hb = __float2bfloat16_rn(x);
    h = __bfloat162float(hb);
    l = x - h;
}

__device__ __forceinline__ void mma_bf16(float d[4], const uint32_t a[4],
                                         uint32_t b0, uint32_t b1) {
    asm volatile(
        "mma.sync.aligned.m16n8k16.row.col.f32.bf16.bf16.f32 "
        "{%0,%1,%2,%3},{%4,%5,%6,%7},{%8,%9},{%0,%1,%2,%3};"
        : "+f"(d[0]), "+f"(d[1]), "+f"(d[2]), "+f"(d[3])
        : "r"(a[0]), "r"(a[1]), "r"(a[2]), "r"(a[3]), "r"(b0), "r"(b1));
}

// ---- scratch ----
__device__ float g_agg[BB * KK * CC];
__device__ float g_asum[BB * KK];

__global__ void zero_scratch() {
    int i = blockIdx.x * blockDim.x + threadIdx.x;
    const int tot = BB * KK * CC + BB * KK;
    for (; i < tot; i += gridDim.x * blockDim.x) {
        if (i < BB * KK * CC) g_agg[i] = 0.0f;
        else g_asum[i - BB * KK * CC] = 0.0f;
    }
}

// ---------------------------------------------------------------------------
__global__ __launch_bounds__(256, 1) void netvlad_main(
    const float* __restrict__ x,
    const float* __restrict__ conv_w,
    const float* __restrict__ conv_b)
{
    extern __shared__ uint32_t smu[];

    const int t = threadIdx.x;
    const int wid = t >> 5;
    const int lane = t & 31;
    const int g = lane >> 2;
    const int tig = lane & 3;
    const int b = blockIdx.y;
    const int split = blockIdx.x;

    // phase-1: warp tile 32k x 32n, cgrp halves contraction c
    const int cgrp = wid >> 2;
    const int kb1 = (wid & 1) * 32;
    const int nb1 = ((wid >> 1) & 1) * 32;
    // phase-3: warp tile 64k x 32c, 2-way n-contraction split
    const int nh3 = wid >> 2;            // n-half: word offset nh3*16
    const int cb3 = (wid & 3) * 32;
    // softmax mapping
    const int sn = t >> 2;
    const int sub = t & 3;

    // ---- stage W (hi/lo bf16, c-paired) ----
    {
        const int k = t >> 2;
        const int c8 = (t & 3) * 8;
        #pragma unroll
        for (int p = 0; p < 4; p++) {
            int c = c8 + 32 * p;
            float4 va = *(const float4*)(conv_w + k * CC + c);
            float4 vb = *(const float4*)(conv_w + k * CC + c + 4);
            float h[8], l[8];
            bsplit(va.x, h[0], l[0]); bsplit(va.y, h[1], l[1]);
            bsplit(va.z, h[2], l[2]); bsplit(va.w, h[3], l[3]);
            bsplit(vb.x, h[4], l[4]); bsplit(vb.y, h[5], l[5]);
            bsplit(vb.z, h[6], l[6]); bsplit(vb.w, h[7], l[7]);
            uint4 uh = make_uint4(pkbf(h[0], h[1]), pkbf(h[2], h[3]),
                                  pkbf(h[4], h[5]), pkbf(h[6], h[7]));
            uint4 ul = make_uint4(pkbf(l[0], l[1]), pkbf(l[2], l[3]),
                                  pkbf(l[4], l[5]), pkbf(l[6], l[7]));
            *(uint4*)&smu[U_WH + k * WSTR + c / 2] = uh;
            *(uint4*)&smu[U_WL + k * WSTR + c / 2] = ul;
        }
    }

    float biasr[16];
    #pragma unroll
    for (int i = 0; i < 16; i++) biasr[i] = conv_b[sub + 4 * i];

    float asum_part[16];
    #pragma unroll
    for (int i = 0; i < 16; i++) asum_part[i] = 0.0f;

    // d3[mf 4][nf 4][4] — warp tile 64k x 32c
    float d3[4][4][4];
    #pragma unroll
    for (int mf = 0; mf < 4; mf++)
        #pragma unroll
        for (int nf = 0; nf < 4; nf++)
            #pragma unroll
            for (int q = 0; q < 4; q++) d3[mf][nf][q] = 0.0f;

    const float* xb = x + (size_t)b * CC * NN;
    const int n_base = split * (NN / SPLITS);

    __syncthreads();

    for (int tile = 0; tile < TILES; tile++) {
        const int n0 = n_base + tile * TN;

        // ---- stage x tile: c-paired hi/lo (P1-B) and n-paired hi (P3-B) ----
        {
            const int q0 = t >> 4;           // cpair 0..15
            const int i4 = (t & 15) * 4;     // n offset
            #pragma unroll
            for (int p = 0; p < 4; p++) {
                int cp = q0 + 16 * p;
                float4 v0 = *(const float4*)(xb + (size_t)(2 * cp) * NN + n0 + i4);
                float4 v1 = *(const float4*)(xb + (size_t)(2 * cp + 1) * NN + n0 + i4);
                float h0[4], l0[4], h1[4], l1[4];
                bsplit(v0.x, h0[0], l0[0]); bsplit(v0.y, h0[1], l0[1]);
                bsplit(v0.z, h0[2], l0[2]); bsplit(v0.w, h0[3], l0[3]);
                bsplit(v1.x, h1[0], l1[0]); bsplit(v1.y, h1[1], l1[1]);
                bsplit(v1.z, h1[2], l1[2]); bsplit(v1.w, h1[3], l1[3]);
                uint4 ch = make_uint4(pkbf(h0[0], h1[0]), pkbf(h0[1], h1[1]),
                                      pkbf(h0[2], h1[2]), pkbf(h0[3], h1[3]));
                uint4 cl = make_uint4(pkbf(l0[0], l1[0]), pkbf(l0[1], l1[1]),
                                      pkbf(l0[2], l1[2]), pkbf(l0[3], l1[3]));
                *(uint4*)&smu[U_XCH + cp * XCSTR + i4] = ch;
                *(uint4*)&smu[U_XCL + cp * XCSTR + i4] = cl;
                uint2 nh0 = make_uint2(pkbf(h0[0], h0[1]), pkbf(h0[2], h0[3]));
                uint2 nh1 = make_uint2(pkbf(h1[0], h1[1]), pkbf(h1[2], h1[3]));
                *(uint2*)&smu[U_XNH + (2 * cp) * XNSTR + i4 / 2] = nh0;
                *(uint2*)&smu[U_XNH + (2 * cp + 1) * XNSTR + i4 / 2] = nh1;
            }
        }
        __syncthreads();

        // ---- phase 1: D1[k][n] = W @ x over c-half, 3-pass bf16 split ----
        {
            float d1[2][4][4];
            #pragma unroll
            for (int mf = 0; mf < 2; mf++)
                #pragma unroll
                for (int nf = 0; nf < 4; nf++)
                    #pragma unroll
                    for (int q = 0; q < 4; q++) d1[mf][nf][q] = 0.0f;

            #pragma unroll
            for (int pass = 0; pass < 3; pass++) {
                const uint32_t Ab = (pass == 2) ? U_WL : U_WH;
                const uint32_t Bb = (pass == 1) ? U_XCL : U_XCH;
                #pragma unroll
                for (int s = 0; s < 4; s++) {
                    const int cp0 = cgrp * 32 + s * 8;
                    uint32_t af[2][4];
                    #pragma unroll
                    for (int mf = 0; mf < 2; mf++) {
                        int row = kb1 + mf * 16 + g;
                        af[mf][0] = smu[Ab + row * WSTR + cp0 + tig];
                        af[mf][1] = smu[Ab + (row + 8) * WSTR + cp0 + tig];
                        af[mf][2] = smu[Ab + row * WSTR + cp0 + 4 + tig];
                        af[mf][3] = smu[Ab + (row + 8) * WSTR + cp0 + 4 + tig];
                    }
                    #pragma unroll
                    for (int nf = 0; nf < 4; nf++) {
                        int col = nb1 + nf * 8 + g;
                        uint32_t b0 = smu[Bb + (cp0 + tig) * XCSTR + col];
                        uint32_t b1 = smu[Bb + (cp0 + 4 + tig) * XCSTR + col];
                        mma_bf16(d1[0][nf], af[0], b0, b1);
                        mma_bf16(d1[1][nf], af[1], b0, b1);
                    }
                }
            }
            float* sL = (float*)&smu[cgrp ? U_L1 : U_L0];
            #pragma unroll
            for (int mf = 0; mf < 2; mf++) {
                #pragma unroll
                for (int nf = 0; nf < 4; nf++) {
                    int kk = kb1 + mf * 16 + g;
                    int nn = nb1 + nf * 8 + 2 * tig;
                    sL[nn * LDL + kk]           = d1[mf][nf][0];
                    sL[(nn + 1) * LDL + kk]     = d1[mf][nf][1];
                    sL[nn * LDL + kk + 8]       = d1[mf][nf][2];
                    sL[(nn + 1) * LDL + kk + 8] = d1[mf][nf][3];
                }
            }
        }
        __syncthreads();

        // ---- softmax(relu) over k per column n (no max-sub: logits>=0, bounded) ----
        {
            const float* sL0 = (const float*)&smu[U_L0];
            const float* sL1 = (const float*)&smu[U_L1];
            float av[16];
            float s = 0.0f;
            #pragma unroll
            for (int i = 0; i < 16; i++) {
                int k = sub + 4 * i;
                float v = sL0[sn * LDL + k] + sL1[sn * LDL + k] + biasr[i];
                av[i] = __expf(fmaxf(v, 0.0f));
                s += av[i];
            }
            s += __shfl_xor_sync(0xffffffffu, s, 1);
            s += __shfl_xor_sync(0xffffffffu, s, 2);
            float inv = 1.0f / s;
            unsigned short* aH = (unsigned short*)&smu[U_AH];
            unsigned short* aL = (unsigned short*)&smu[U_AL];
            #pragma unroll
            for (int i = 0; i < 16; i++) {
                int k = sub + 4 * i;
                float a = av[i] * inv;
                asum_part[i] += a;
                __nv_bfloat16 hb = __float2bfloat16_rn(a);
                float hf = __bfloat162float(hb);
                __nv_bfloat16 lb = __float2bfloat16_rn(a - hf);
                aH[k * (2 * AST32) + sn] = __bfloat16_as_ushort(hb);
                aL[k * (2 * AST32) + sn] = __bfloat16_as_ushort(lb);
            }
        }
        __syncthreads();

        // ---- phase 3: D3[k][c] += a @ x^T; 2-pass (a_hi, a_lo) vs x_hi ----
        #pragma unroll
        for (int pass = 0; pass < 2; pass++) {
            const uint32_t Ab = pass ? U_AL : U_AH;
            #pragma unroll
            for (int s = 0; s < 2; s++) {
                const int np0 = nh3 * 16 + s * 8;
                uint32_t af[4][4];
                #pragma unroll
                for (int mf = 0; mf < 4; mf++) {
                    int row = mf * 16 + g;
                    af[mf][0] = smu[Ab + row * AST32 + np0 + tig];
                    af[mf][1] = smu[Ab + (row + 8) * AST32 + np0 + tig];
                    af[mf][2] = smu[Ab + row * AST32 + np0 + 4 + tig];
                    af[mf][3] = smu[Ab + (row + 8) * AST32 + np0 + 4 + tig];
                }
                #pragma unroll
                for (int nf = 0; nf < 4; nf++) {
                    int c = cb3 + nf * 8 + g;
                    uint32_t b0 = smu[U_XNH + c * XNSTR + np0 + tig];
                    uint32_t b1 = smu[U_XNH + c * XNSTR + np0 + 4 + tig];
                    #pragma unroll
                    for (int mf = 0; mf < 4; mf++)
                        mma_bf16(d3[mf][nf], af[mf], b0, b1);
                }
            }
        }
        __syncthreads();   // x/a/L buffers free for next tile
    }

    // ---- commit D3 to global (both n-halves add same addrs via atomics) ----
    float* agg = g_agg + (size_t)b * KK * CC;
    #pragma unroll
    for (int mf = 0; mf < 4; mf++) {
        #pragma unroll
        for (int nf = 0; nf < 4; nf++) {
            int k0 = mf * 16 + g;
            int c0 = cb3 + nf * 8 + 2 * tig;
            atomicAdd(&agg[k0 * CC + c0],           d3[mf][nf][0]);
            atomicAdd(&agg[k0 * CC + c0 + 1],       d3[mf][nf][1]);
            atomicAdd(&agg[(k0 + 8) * CC + c0],     d3[mf][nf][2]);
            atomicAdd(&agg[(k0 + 8) * CC + c0 + 1], d3[mf][nf][3]);
        }
    }
    #pragma unroll
    for (int i = 0; i < 16; i++) {
        float v = asum_part[i];
        v += __shfl_xor_sync(0xffffffffu, v, 4);
        v += __shfl_xor_sync(0xffffffffu, v, 8);
        v += __shfl_xor_sync(0xffffffffu, v, 16);
        if (lane < 4)
            atomicAdd(&g_asum[b * KK + sub + 4 * i], v);
    }
}

// ---------------------------------------------------------------------------
__global__ __launch_bounds__(256) void netvlad_finalize(
    const float* __restrict__ centroids,
    float* __restrict__ out)
{
    __shared__ float sred[8];
    const int b = blockIdx.x;
    const int t = threadIdx.x;
    const int lane = t & 31;
    const int w = t >> 5;

    const float* agg = g_agg + (size_t)b * KK * CC;
    const float* as  = g_asum + b * KK;

    float v[8][4];
    float gss = 0.0f;

    #pragma unroll
    for (int r = 0; r < 8; r++) {
        const int k = w * 8 + r;
        const float s = as[k];
        const int c4 = lane * 4;
        float4 a = *(const float4*)&agg[k * CC + c4];
        float4 cn = *(const float4*)&centroids[k * CC + c4];
        v[r][0] = a.x - s * cn.x;
        v[r][1] = a.y - s * cn.y;
        v[r][2] = a.z - s * cn.z;
        v[r][3] = a.w - s * cn.w;
        float ss = v[r][0]*v[r][0] + v[r][1]*v[r][1] + v[r][2]*v[r][2] + v[r][3]*v[r][3];
        #pragma unroll
        for (int off = 16; off > 0; off >>= 1)
            ss += __shfl_xor_sync(0xffffffffu, ss, off);
        float scale = 1.0f / fmaxf(sqrtf(ss), EPSV);
        #pragma unroll
        for (int j = 0; j < 4; j++) { v[r][j] *= scale; gss += v[r][j] * v[r][j]; }
    }

    #pragma unroll
    for (int off = 16; off > 0; off >>= 1)
        gss += __shfl_xor_sync(0xffffffffu, gss, off);
    if (lane == 0) sred[w] = gss;
    __syncthreads();
    float tot = 0.0f;
    #pragma unroll
    for (int i = 0; i < 8; i++) tot += sred[i];
    float gscale = 1.0f / fmaxf(sqrtf(tot), EPSV);

    #pragma unroll
    for (int r = 0; r < 8; r++) {
        const int k = w * 8 + r;
        float4 o;
        o.x = v[r][0] * gscale; o.y = v[r][1] * gscale;
        o.z = v[r][2] * gscale; o.w = v[r][3] * gscale;
        *(float4*)&out[(size_t)b * KK * CC + k * CC + lane * 4] = o;
    }
}

// ---------------------------------------------------------------------------
extern "C" void kernel_launch(void* const* d_in, const int* in_sizes, int n_in,
                              void* d_out, int out_size)
{
    const float* x         = (const float*)d_in[0];
    const float* conv_w    = (const float*)d_in[1];
    const float* conv_b    = (const float*)d_in[2];
    const float* centroids = (const float*)d_in[3];
    float* out = (float*)d_out;

    const int smem_bytes = SMEM_U32 * 4;   // 143360
    static bool attr_set = false;
    if (!attr_set) {
        cudaFuncSetAttribute(netvlad_main,
                             cudaFuncAttributeMaxDynamicSharedMemorySize,
                             smem_bytes);
        attr_set = true;
    }

    zero_scratch<<<264, 1024>>>();
    dim3 grid(SPLITS, BB);
    netvlad_main<<<grid, 256, smem_bytes>>>(x, conv_w, conv_b);
    netvlad_finalize<<<BB, 256>>>(centroids, out);
}

// round 10
// speedup vs baseline: 3.1130x; 1.3485x over previous
#include <cuda_runtime.h>
#include <cuda_fp16.h>
#include <cstdint>

#define BB 32
#define CC 128
#define NN 16384
#define KK 64
#define TN 64
#define SPLITS 32
#define TILES ((NN / SPLITS) / TN)   // 8 tiles per CTA
#define EPSV 1e-12f

// ---- SMEM layout (uint32 units) ----
#define WSTR   68     // W pairs [k=64][cp=64]
#define XCSTR  72     // x c-paired [cp=64][n=64]
#define XNSTR  36     // x n-paired [c=128][np=32]
#define AST32  36     // a n-paired [k=64][np=32]
#define LDL    68     // logits float [n=64][k]
#define U_WH   0
#define U_WL   (U_WH  + 64 * WSTR)
#define U_XCH  (U_WL  + 64 * WSTR)
#define U_XCL  (U_XCH + 64 * XCSTR)
#define U_XNH  (U_XCL + 64 * XCSTR)
#define U_L0   (U_XNH + 128 * XNSTR)
#define U_L1   (U_L0  + 64 * LDL)
#define U_A    (U_L1  + 64 * LDL)
#define SMEM_U32 (U_A + 64 * AST32)   // 33536 u32 = 134144 B

__device__ __forceinline__ uint32_t pkhf(float lo, float hi) {
    unsigned short a = __half_as_ushort(__float2half_rn(lo));
    unsigned short b = __half_as_ushort(__float2half_rn(hi));
    return (uint32_t)a | ((uint32_t)b << 16);
}
__device__ __forceinline__ void hsplit(float x, float& h, float& l) {
    __half hb = __float2half_rn(x);
    h = __half2float(hb);
    l = x - h;
}

__device__ __forceinline__ void mma_f16(float d[4], const uint32_t a[4],
                                        uint32_t b0, uint32_t b1) {
    asm volatile(
        "mma.sync.aligned.m16n8k16.row.col.f32.f16.f16.f32 "
        "{%0,%1,%2,%3},{%4,%5,%6,%7},{%8,%9},{%0,%1,%2,%3};"
        : "+f"(d[0]), "+f"(d[1]), "+f"(d[2]), "+f"(d[3])
        : "r"(a[0]), "r"(a[1]), "r"(a[2]), "r"(a[3]), "r"(b0), "r"(b1));
}

// ---- scratch ----
__device__ float g_agg[BB * KK * CC];
__device__ float g_asum[BB * KK];

__global__ void zero_scratch() {
    int i = blockIdx.x * blockDim.x + threadIdx.x;
    const int tot = BB * KK * CC + BB * KK;
    for (; i < tot; i += gridDim.x * blockDim.x) {
        if (i < BB * KK * CC) g_agg[i] = 0.0f;
        else g_asum[i - BB * KK * CC] = 0.0f;
    }
}

// ---------------------------------------------------------------------------
__global__ __launch_bounds__(256, 1) void netvlad_main(
    const float* __restrict__ x,
    const float* __restrict__ conv_w,
    const float* __restrict__ conv_b)
{
    extern __shared__ uint32_t smu[];

    const int t = threadIdx.x;
    const int wid = t >> 5;
    const int lane = t & 31;
    const int g = lane >> 2;
    const int tig = lane & 3;
    const int b = blockIdx.y;
    const int split = blockIdx.x;

    // phase-1: warp tile 32k x 32n, cgrp halves contraction c
    const int cgrp = wid >> 2;
    const int kb1 = (wid & 1) * 32;
    const int nb1 = ((wid >> 1) & 1) * 32;
    // phase-3: warp tile 64k x 32c, 2-way n-contraction split
    const int nh3 = wid >> 2;
    const int cb3 = (wid & 3) * 32;
    // softmax mapping
    const int sn = t >> 2;
    const int sub = t & 3;

    // ---- stage W (hi/lo fp16, c-paired) ----
    {
        const int k = t >> 2;
        const int c8 = (t & 3) * 8;
        #pragma unroll
        for (int p = 0; p < 4; p++) {
            int c = c8 + 32 * p;
            float4 va = *(const float4*)(conv_w + k * CC + c);
            float4 vb = *(const float4*)(conv_w + k * CC + c + 4);
            float h[8], l[8];
            hsplit(va.x, h[0], l[0]); hsplit(va.y, h[1], l[1]);
            hsplit(va.z, h[2], l[2]); hsplit(va.w, h[3], l[3]);
            hsplit(vb.x, h[4], l[4]); hsplit(vb.y, h[5], l[5]);
            hsplit(vb.z, h[6], l[6]); hsplit(vb.w, h[7], l[7]);
            uint4 uh = make_uint4(pkhf(h[0], h[1]), pkhf(h[2], h[3]),
                                  pkhf(h[4], h[5]), pkhf(h[6], h[7]));
            uint4 ul = make_uint4(pkhf(l[0], l[1]), pkhf(l[2], l[3]),
                                  pkhf(l[4], l[5]), pkhf(l[6], l[7]));
            *(uint4*)&smu[U_WH + k * WSTR + c / 2] = uh;
            *(uint4*)&smu[U_WL + k * WSTR + c / 2] = ul;
        }
    }

    float biasr[16];
    #pragma unroll
    for (int i = 0; i < 16; i++) biasr[i] = conv_b[sub + 4 * i];

    float asum_part[16];
    #pragma unroll
    for (int i = 0; i < 16; i++) asum_part[i] = 0.0f;

    float d3[4][4][4];
    #pragma unroll
    for (int mf = 0; mf < 4; mf++)
        #pragma unroll
        for (int nf = 0; nf < 4; nf++)
            #pragma unroll
            for (int q = 0; q < 4; q++) d3[mf][nf][q] = 0.0f;

    const float* xb = x + (size_t)b * CC * NN;
    const int n_base = split * (NN / SPLITS);

    // staging thread mapping
    const int q0 = t >> 4;           // cpair 0..15
    const int i4 = (t & 15) * 4;     // n offset

    // ---- prefetch tile 0 into registers ----
    float4 pf[8];
    #pragma unroll
    for (int p = 0; p < 4; p++) {
        int cp = q0 + 16 * p;
        pf[2 * p]     = *(const float4*)(xb + (size_t)(2 * cp) * NN + n_base + i4);
        pf[2 * p + 1] = *(const float4*)(xb + (size_t)(2 * cp + 1) * NN + n_base + i4);
    }

    __syncthreads();

    for (int tile = 0; tile < TILES; tile++) {
        // ---- stage x tile from prefetch regs: c-paired hi/lo + n-paired hi ----
        {
            #pragma unroll
            for (int p = 0; p < 4; p++) {
                int cp = q0 + 16 * p;
                float4 v0 = pf[2 * p];
                float4 v1 = pf[2 * p + 1];
                float h0[4], l0[4], h1[4], l1[4];
                hsplit(v0.x, h0[0], l0[0]); hsplit(v0.y, h0[1], l0[1]);
                hsplit(v0.z, h0[2], l0[2]); hsplit(v0.w, h0[3], l0[3]);
                hsplit(v1.x, h1[0], l1[0]); hsplit(v1.y, h1[1], l1[1]);
                hsplit(v1.z, h1[2], l1[2]); hsplit(v1.w, h1[3], l1[3]);
                uint4 ch = make_uint4(pkhf(h0[0], h1[0]), pkhf(h0[1], h1[1]),
                                      pkhf(h0[2], h1[2]), pkhf(h0[3], h1[3]));
                uint4 cl = make_uint4(pkhf(l0[0], l1[0]), pkhf(l0[1], l1[1]),
                                      pkhf(l0[2], l1[2]), pkhf(l0[3], l1[3]));
                *(uint4*)&smu[U_XCH + cp * XCSTR + i4] = ch;
                *(uint4*)&smu[U_XCL + cp * XCSTR + i4] = cl;
                uint2 nh0 = make_uint2(pkhf(h0[0], h0[1]), pkhf(h0[2], h0[3]));
                uint2 nh1 = make_uint2(pkhf(h1[0], h1[1]), pkhf(h1[2], h1[3]));
                *(uint2*)&smu[U_XNH + (2 * cp) * XNSTR + i4 / 2] = nh0;
                *(uint2*)&smu[U_XNH + (2 * cp + 1) * XNSTR + i4 / 2] = nh1;
            }
        }
        // ---- issue next tile's global loads (latency overlaps P1/P3) ----
        if (tile + 1 < TILES) {
            const int n1 = n_base + (tile + 1) * TN;
            #pragma unroll
            for (int p = 0; p < 4; p++) {
                int cp = q0 + 16 * p;
                pf[2 * p]     = *(const float4*)(xb + (size_t)(2 * cp) * NN + n1 + i4);
                pf[2 * p + 1] = *(const float4*)(xb + (size_t)(2 * cp + 1) * NN + n1 + i4);
            }
        }
        __syncthreads();

        // ---- phase 1: D1[k][n] = W @ x over c-half, 3-pass fp16 split ----
        {
            float d1[2][4][4];
            #pragma unroll
            for (int mf = 0; mf < 2; mf++)
                #pragma unroll
                for (int nf = 0; nf < 4; nf++)
                    #pragma unroll
                    for (int q = 0; q < 4; q++) d1[mf][nf][q] = 0.0f;

            #pragma unroll
            for (int pass = 0; pass < 3; pass++) {
                const uint32_t Ab = (pass == 2) ? U_WL : U_WH;
                const uint32_t Bb = (pass == 1) ? U_XCL : U_XCH;
                #pragma unroll
                for (int s = 0; s < 4; s++) {
                    const int cp0 = cgrp * 32 + s * 8;
                    uint32_t af[2][4];
                    #pragma unroll
                    for (int mf = 0; mf < 2; mf++) {
                        int row = kb1 + mf * 16 + g;
                        af[mf][0] = smu[Ab + row * WSTR + cp0 + tig];
                        af[mf][1] = smu[Ab + (row + 8) * WSTR + cp0 + tig];
                        af[mf][2] = smu[Ab + row * WSTR + cp0 + 4 + tig];
                        af[mf][3] = smu[Ab + (row + 8) * WSTR + cp0 + 4 + tig];
                    }
                    #pragma unroll
                    for (int nf = 0; nf < 4; nf++) {
                        int col = nb1 + nf * 8 + g;
                        uint32_t b0 = smu[Bb + (cp0 + tig) * XCSTR + col];
                        uint32_t b1 = smu[Bb + (cp0 + 4 + tig) * XCSTR + col];
                        mma_f16(d1[0][nf], af[0], b0, b1);
                        mma_f16(d1[1][nf], af[1], b0, b1);
                    }
                }
            }
            float* sL = (float*)&smu[cgrp ? U_L1 : U_L0];
            #pragma unroll
            for (int mf = 0; mf < 2; mf++) {
                #pragma unroll
                for (int nf = 0; nf < 4; nf++) {
                    int kk = kb1 + mf * 16 + g;
                    int nn = nb1 + nf * 8 + 2 * tig;
                    sL[nn * LDL + kk]           = d1[mf][nf][0];
                    sL[(nn + 1) * LDL + kk]     = d1[mf][nf][1];
                    sL[nn * LDL + kk + 8]       = d1[mf][nf][2];
                    sL[(nn + 1) * LDL + kk + 8] = d1[mf][nf][3];
                }
            }
        }
        __syncthreads();

        // ---- softmax(relu) over k per column n; a stored as single fp16 ----
        {
            const float* sL0 = (const float*)&smu[U_L0];
            const float* sL1 = (const float*)&smu[U_L1];
            float av[16];
            float s = 0.0f;
            #pragma unroll
            for (int i = 0; i < 16; i++) {
                int k = sub + 4 * i;
                float v = sL0[sn * LDL + k] + sL1[sn * LDL + k] + biasr[i];
                av[i] = __expf(fmaxf(v, 0.0f));
                s += av[i];
            }
            s += __shfl_xor_sync(0xffffffffu, s, 1);
            s += __shfl_xor_sync(0xffffffffu, s, 2);
            float inv = 1.0f / s;
            unsigned short* aP = (unsigned short*)&smu[U_A];
            #pragma unroll
            for (int i = 0; i < 16; i++) {
                int k = sub + 4 * i;
                float a = av[i] * inv;
                asum_part[i] += a;
                aP[k * (2 * AST32) + sn] = __half_as_ushort(__float2half_rn(a));
            }
        }
        __syncthreads();

        // ---- phase 3: D3[k][c] += a @ x^T; single fp16 pass ----
        #pragma unroll
        for (int s = 0; s < 2; s++) {
            const int np0 = nh3 * 16 + s * 8;
            uint32_t af[4][4];
            #pragma unroll
            for (int mf = 0; mf < 4; mf++) {
                int row = mf * 16 + g;
                af[mf][0] = smu[U_A + row * AST32 + np0 + tig];
                af[mf][1] = smu[U_A + (row + 8) * AST32 + np0 + tig];
                af[mf][2] = smu[U_A + row * AST32 + np0 + 4 + tig];
                af[mf][3] = smu[U_A + (row + 8) * AST32 + np0 + 4 + tig];
            }
            #pragma unroll
            for (int nf = 0; nf < 4; nf++) {
                int c = cb3 + nf * 8 + g;
                uint32_t b0 = smu[U_XNH + c * XNSTR + np0 + tig];
                uint32_t b1 = smu[U_XNH + c * XNSTR + np0 + 4 + tig];
                #pragma unroll
                for (int mf = 0; mf < 4; mf++)
                    mma_f16(d3[mf][nf], af[mf], b0, b1);
            }
        }
        __syncthreads();   // x/a/L buffers free for next tile
    }

    // ---- commit D3 to global ----
    float* agg = g_agg + (size_t)b * KK * CC;
    #pragma unroll
    for (int mf = 0; mf < 4; mf++) {
        #pragma unroll
        for (int nf = 0; nf < 4; nf++) {
            int k0 = mf * 16 + g;
            int c0 = cb3 + nf * 8 + 2 * tig;
            atomicAdd(&agg[k0 * CC + c0],           d3[mf][nf][0]);
            atomicAdd(&agg[k0 * CC + c0 + 1],       d3[mf][nf][1]);
            atomicAdd(&agg[(k0 + 8) * CC + c0],     d3[mf][nf][2]);
            atomicAdd(&agg[(k0 + 8) * CC + c0 + 1], d3[mf][nf][3]);
        }
    }
    #pragma unroll
    for (int i = 0; i < 16; i++) {
        float v = asum_part[i];
        v += __shfl_xor_sync(0xffffffffu, v, 4);
        v += __shfl_xor_sync(0xffffffffu, v, 8);
        v += __shfl_xor_sync(0xffffffffu, v, 16);
        if (lane < 4)
            atomicAdd(&g_asum[b * KK + sub + 4 * i], v);
    }
}

// ---------------------------------------------------------------------------
__global__ __launch_bounds__(256) void netvlad_finalize(
    const float* __restrict__ centroids,
    float* __restrict__ out)
{
    __shared__ float sred[8];
    const int b = blockIdx.x;
    const int t = threadIdx.x;
    const int lane = t & 31;
    const int w = t >> 5;

    const float* agg = g_agg + (size_t)b * KK * CC;
    const float* as  = g_asum + b * KK;

    float v[8][4];
    float gss = 0.0f;

    #pragma unroll
    for (int r = 0; r < 8; r++) {
        const int k = w * 8 + r;
        const float s = as[k];
        const int c4 = lane * 4;
        float4 a = *(const float4*)&agg[k * CC + c4];
        float4 cn = *(const float4*)&centroids[k * CC + c4];
        v[r][0] = a.x - s * cn.x;
        v[r][1] = a.y - s * cn.y;
        v[r][2] = a.z - s * cn.z;
        v[r][3] = a.w - s * cn.w;
        float ss = v[r][0]*v[r][0] + v[r][1]*v[r][1] + v[r][2]*v[r][2] + v[r][3]*v[r][3];
        #pragma unroll
        for (int off = 16; off > 0; off >>= 1)
            ss += __shfl_xor_sync(0xffffffffu, ss, off);
        float scale = 1.0f / fmaxf(sqrtf(ss), EPSV);
        #pragma unroll
        for (int j = 0; j < 4; j++) { v[r][j] *= scale; gss += v[r][j] * v[r][j]; }
    }

    #pragma unroll
    for (int off = 16; off > 0; off >>= 1)
        gss += __shfl_xor_sync(0xffffffffu, gss, off);
    if (lane == 0) sred[w] = gss;
    __syncthreads();
    float tot = 0.0f;
    #pragma unroll
    for (int i = 0; i < 8; i++) tot += sred[i];
    float gscale = 1.0f / fmaxf(sqrtf(tot), EPSV);

    #pragma unroll
    for (int r = 0; r < 8; r++) {
        const int k = w * 8 + r;
        float4 o;
        o.x = v[r][0] * gscale; o.y = v[r][1] * gscale;
        o.z = v[r][2] * gscale; o.w = v[r][3] * gscale;
        *(float4*)&out[(size_t)b * KK * CC + k * CC + lane * 4] = o;
    }
}

// ---------------------------------------------------------------------------
extern "C" void kernel_launch(void* const* d_in, const int* in_sizes, int n_in,
                              void* d_out, int out_size)
{
    const float* x         = (const float*)d_in[0];
    const float* conv_w    = (const float*)d_in[1];
    const float* conv_b    = (const float*)d_in[2];
    const float* centroids = (const float*)d_in[3];
    float* out = (float*)d_out;

    const int smem_bytes = SMEM_U32 * 4;   // 134144
    static bool attr_set = false;
    if (!attr_set) {
        cudaFuncSetAttribute(netvlad_main,
                             cudaFuncAttributeMaxDynamicSharedMemorySize,
                             smem_bytes);
        attr_set = true;
    }

    zero_scratch<<<264, 1024>>>();
    dim3 grid(SPLITS, BB);
    netvlad_main<<<grid, 256, smem_bytes>>>(x, conv_w, conv_b);
    netvlad_finalize<<<BB, 256>>>(centroids, out);
}

// round 13
// speedup vs baseline: 3.6382x; 1.1687x over previous
#include <cuda_runtime.h>
#include <cuda_fp16.h>
#include <cstdint>

#define BB 32
#define CC 128
#define NN 16384
#define KK 64
#define TN 64
#define SPLITS 32
#define TILES ((NN / SPLITS) / TN)   // 8 tiles per CTA
#define EPSV 1e-12f

// ---- SMEM layout (uint32 units) ----
#define WSTR   68     // W pairs [k=64][cp=64]
#define XCSTR  72     // x c-paired [cp=64][n=64]
#define XNSTR  36     // x n-paired [c=128][np=32]
#define AST32  36     // a n-paired [k=64][np=32]
#define LDL    68     // logits float [n=64][k]
#define U_WH   0
#define U_WL   (U_WH  + 64 * WSTR)
#define U_XCH  (U_WL  + 64 * WSTR)
#define U_XNH  (U_XCH + 64 * XCSTR)
#define U_L0   (U_XNH + 128 * XNSTR)
#define U_L1   (U_L0  + 64 * LDL)
#define U_A    (U_L1  + 64 * LDL)
#define SMEM_U32 (U_A + 64 * AST32)   // 28928 u32 = 115712 B

__device__ __forceinline__ uint32_t pk2u(unsigned short a, unsigned short b) {
    return (uint32_t)a | ((uint32_t)b << 16);
}
__device__ __forceinline__ void hsplit(float x, float& h, float& l) {
    __half hb = __float2half_rn(x);
    h = __half2float(hb);
    l = x - h;
}

__device__ __forceinline__ void mma_f16(float d[4], const uint32_t a[4],
                                        uint32_t b0, uint32_t b1) {
    asm volatile(
        "mma.sync.aligned.m16n8k16.row.col.f32.f16.f16.f32 "
        "{%0,%1,%2,%3},{%4,%5,%6,%7},{%8,%9},{%0,%1,%2,%3};"
        : "+f"(d[0]), "+f"(d[1]), "+f"(d[2]), "+f"(d[3])
        : "r"(a[0]), "r"(a[1]), "r"(a[2]), "r"(a[3]), "r"(b0), "r"(b1));
}

// ---- scratch ----
__device__ float g_agg[BB * KK * CC];
__device__ float g_asum[BB * KK];

__global__ void zero_scratch() {
    int i = blockIdx.x * blockDim.x + threadIdx.x;
    const int tot = BB * KK * CC + BB * KK;
    for (; i < tot; i += gridDim.x * blockDim.x) {
        if (i < BB * KK * CC) g_agg[i] = 0.0f;
        else g_asum[i - BB * KK * CC] = 0.0f;
    }
}

// ---------------------------------------------------------------------------
__global__ __launch_bounds__(256, 1) void netvlad_main(
    const float* __restrict__ x,
    const float* __restrict__ conv_w,
    const float* __restrict__ conv_b)
{
    extern __shared__ uint32_t smu[];

    const int t = threadIdx.x;
    const int wid = t >> 5;
    const int lane = t & 31;
    const int g = lane >> 2;
    const int tig = lane & 3;
    const int b = blockIdx.y;
    const int split = blockIdx.x;

    // phase-1: warp tile 32k x 32n, cgrp halves contraction c
    const int cgrp = wid >> 2;
    const int kb1 = (wid & 1) * 32;
    const int nb1 = ((wid >> 1) & 1) * 32;
    // phase-3: warp tile 64k x 32c, 2-way n-contraction split
    const int nh3 = wid >> 2;
    const int cb3 = (wid & 3) * 32;
    // softmax mapping
    const int sn = t >> 2;
    const int sub = t & 3;

    // ---- stage W (hi/lo fp16, c-paired) ----
    {
        const int k = t >> 2;
        const int c8 = (t & 3) * 8;
        #pragma unroll
        for (int p = 0; p < 4; p++) {
            int c = c8 + 32 * p;
            float4 va = *(const float4*)(conv_w + k * CC + c);
            float4 vb = *(const float4*)(conv_w + k * CC + c + 4);
            float h[8], l[8];
            hsplit(va.x, h[0], l[0]); hsplit(va.y, h[1], l[1]);
            hsplit(va.z, h[2], l[2]); hsplit(va.w, h[3], l[3]);
            hsplit(vb.x, h[4], l[4]); hsplit(vb.y, h[5], l[5]);
            hsplit(vb.z, h[6], l[6]); hsplit(vb.w, h[7], l[7]);
            uint4 uh, ul;
            uh.x = pk2u(__half_as_ushort(__float2half_rn(h[0])), __half_as_ushort(__float2half_rn(h[1])));
            uh.y = pk2u(__half_as_ushort(__float2half_rn(h[2])), __half_as_ushort(__float2half_rn(h[3])));
            uh.z = pk2u(__half_as_ushort(__float2half_rn(h[4])), __half_as_ushort(__float2half_rn(h[5])));
            uh.w = pk2u(__half_as_ushort(__float2half_rn(h[6])), __half_as_ushort(__float2half_rn(h[7])));
            ul.x = pk2u(__half_as_ushort(__float2half_rn(l[0])), __half_as_ushort(__float2half_rn(l[1])));
            ul.y = pk2u(__half_as_ushort(__float2half_rn(l[2])), __half_as_ushort(__float2half_rn(l[3])));
            ul.z = pk2u(__half_as_ushort(__float2half_rn(l[4])), __half_as_ushort(__float2half_rn(l[5])));
            ul.w = pk2u(__half_as_ushort(__float2half_rn(l[6])), __half_as_ushort(__float2half_rn(l[7])));
            *(uint4*)&smu[U_WH + k * WSTR + c / 2] = uh;
            *(uint4*)&smu[U_WL + k * WSTR + c / 2] = ul;
        }
    }

    float biasr[16];
    #pragma unroll
    for (int i = 0; i < 16; i++) biasr[i] = conv_b[sub + 4 * i];

    float asum_part[16];
    #pragma unroll
    for (int i = 0; i < 16; i++) asum_part[i] = 0.0f;

    float d3[4][4][4];
    #pragma unroll
    for (int mf = 0; mf < 4; mf++)
        #pragma unroll
        for (int nf = 0; nf < 4; nf++)
            #pragma unroll
            for (int q = 0; q < 4; q++) d3[mf][nf][q] = 0.0f;

    const float* xb = x + (size_t)b * CC * NN;
    const int n_base = split * (NN / SPLITS);

    // staging thread mapping
    const int q0 = t >> 4;           // cpair 0..15
    const int i4 = (t & 15) * 4;     // n offset

    // ---- prefetch tile 0 into registers ----
    float4 pf[8];
    #pragma unroll
    for (int p = 0; p < 4; p++) {
        int cp = q0 + 16 * p;
        pf[2 * p]     = *(const float4*)(xb + (size_t)(2 * cp) * NN + n_base + i4);
        pf[2 * p + 1] = *(const float4*)(xb + (size_t)(2 * cp + 1) * NN + n_base + i4);
    }

    __syncthreads();

    for (int tile = 0; tile < TILES; tile++) {
        // ---- stage x tile (hi fp16 only): c-paired + n-paired ----
        {
            #pragma unroll
            for (int p = 0; p < 4; p++) {
                int cp = q0 + 16 * p;
                float4 v0 = pf[2 * p];
                float4 v1 = pf[2 * p + 1];
                unsigned short u0[4], u1[4];
                u0[0] = __half_as_ushort(__float2half_rn(v0.x));
                u0[1] = __half_as_ushort(__float2half_rn(v0.y));
                u0[2] = __half_as_ushort(__float2half_rn(v0.z));
                u0[3] = __half_as_ushort(__float2half_rn(v0.w));
                u1[0] = __half_as_ushort(__float2half_rn(v1.x));
                u1[1] = __half_as_ushort(__float2half_rn(v1.y));
                u1[2] = __half_as_ushort(__float2half_rn(v1.z));
                u1[3] = __half_as_ushort(__float2half_rn(v1.w));
                // c-paired: word = (even-c, odd-c) per n
                uint4 ch = make_uint4(pk2u(u0[0], u1[0]), pk2u(u0[1], u1[1]),
                                      pk2u(u0[2], u1[2]), pk2u(u0[3], u1[3]));
                *(uint4*)&smu[U_XCH + cp * XCSTR + i4] = ch;
                // n-paired: per c row, word = (even-n, odd-n)
                uint2 nh0 = make_uint2(pk2u(u0[0], u0[1]), pk2u(u0[2], u0[3]));
                uint2 nh1 = make_uint2(pk2u(u1[0], u1[1]), pk2u(u1[2], u1[3]));
                *(uint2*)&smu[U_XNH + (2 * cp) * XNSTR + i4 / 2] = nh0;
                *(uint2*)&smu[U_XNH + (2 * cp + 1) * XNSTR + i4 / 2] = nh1;
            }
        }
        // ---- issue next tile's global loads (latency overlaps P1/P3) ----
        if (tile + 1 < TILES) {
            const int n1 = n_base + (tile + 1) * TN;
            #pragma unroll
            for (int p = 0; p < 4; p++) {
                int cp = q0 + 16 * p;
                pf[2 * p]     = *(const float4*)(xb + (size_t)(2 * cp) * NN + n1 + i4);
                pf[2 * p + 1] = *(const float4*)(xb + (size_t)(2 * cp + 1) * NN + n1 + i4);
            }
        }
        __syncthreads();

        // ---- phase 1: D1[k][n] = (Wh + Wl) @ x_hi over c-half ----
        // B-fragments loaded once, reused for both W passes.
        {
            float d1[2][4][4];
            #pragma unroll
            for (int mf = 0; mf < 2; mf++)
                #pragma unroll
                for (int nf = 0; nf < 4; nf++)
                    #pragma unroll
                    for (int q = 0; q < 4; q++) d1[mf][nf][q] = 0.0f;

            #pragma unroll
            for (int s = 0; s < 4; s++) {
                const int cp0 = cgrp * 32 + s * 8;
                uint32_t afh[2][4], afl[2][4];
                #pragma unroll
                for (int mf = 0; mf < 2; mf++) {
                    int row = kb1 + mf * 16 + g;
                    afh[mf][0] = smu[U_WH + row * WSTR + cp0 + tig];
                    afh[mf][1] = smu[U_WH + (row + 8) * WSTR + cp0 + tig];
                    afh[mf][2] = smu[U_WH + row * WSTR + cp0 + 4 + tig];
                    afh[mf][3] = smu[U_WH + (row + 8) * WSTR + cp0 + 4 + tig];
                    afl[mf][0] = smu[U_WL + row * WSTR + cp0 + tig];
                    afl[mf][1] = smu[U_WL + (row + 8) * WSTR + cp0 + tig];
                    afl[mf][2] = smu[U_WL + row * WSTR + cp0 + 4 + tig];
                    afl[mf][3] = smu[U_WL + (row + 8) * WSTR + cp0 + 4 + tig];
                }
                #pragma unroll
                for (int nf = 0; nf < 4; nf++) {
                    int col = nb1 + nf * 8 + g;
                    uint32_t b0 = smu[U_XCH + (cp0 + tig) * XCSTR + col];
                    uint32_t b1 = smu[U_XCH + (cp0 + 4 + tig) * XCSTR + col];
                    mma_f16(d1[0][nf], afh[0], b0, b1);
                    mma_f16(d1[1][nf], afh[1], b0, b1);
                    mma_f16(d1[0][nf], afl[0], b0, b1);
                    mma_f16(d1[1][nf], afl[1], b0, b1);
                }
            }
            float* sL = (float*)&smu[cgrp ? U_L1 : U_L0];
            #pragma unroll
            for (int mf = 0; mf < 2; mf++) {
                #pragma unroll
                for (int nf = 0; nf < 4; nf++) {
                    int kk = kb1 + mf * 16 + g;
                    int nn = nb1 + nf * 8 + 2 * tig;
                    sL[nn * LDL + kk]           = d1[mf][nf][0];
                    sL[(nn + 1) * LDL + kk]     = d1[mf][nf][1];
                    sL[nn * LDL + kk + 8]       = d1[mf][nf][2];
                    sL[(nn + 1) * LDL + kk + 8] = d1[mf][nf][3];
                }
            }
        }
        __syncthreads();

        // ---- softmax(relu) over k per column n; a stored as single fp16 ----
        {
            const float* sL0 = (const float*)&smu[U_L0];
            const float* sL1 = (const float*)&smu[U_L1];
            float av[16];
            float s = 0.0f;
            #pragma unroll
            for (int i = 0; i < 16; i++) {
                int k = sub + 4 * i;
                float v = sL0[sn * LDL + k] + sL1[sn * LDL + k] + biasr[i];
                av[i] = __expf(fmaxf(v, 0.0f));
                s += av[i];
            }
            s += __shfl_xor_sync(0xffffffffu, s, 1);
            s += __shfl_xor_sync(0xffffffffu, s, 2);
            float inv = 1.0f / s;
            unsigned short* aP = (unsigned short*)&smu[U_A];
            #pragma unroll
            for (int i = 0; i < 16; i++) {
                int k = sub + 4 * i;
                float a = av[i] * inv;
                asum_part[i] += a;
                aP[k * (2 * AST32) + sn] = __half_as_ushort(__float2half_rn(a));
            }
        }
        __syncthreads();

        // ---- phase 3: D3[k][c] += a @ x^T; single fp16 pass ----
        #pragma unroll
        for (int s = 0; s < 2; s++) {
            const int np0 = nh3 * 16 + s * 8;
            uint32_t af[4][4];
            #pragma unroll
            for (int mf = 0; mf < 4; mf++) {
                int row = mf * 16 + g;
                af[mf][0] = smu[U_A + row * AST32 + np0 + tig];
                af[mf][1] = smu[U_A + (row + 8) * AST32 + np0 + tig];
                af[mf][2] = smu[U_A + row * AST32 + np0 + 4 + tig];
                af[mf][3] = smu[U_A + (row + 8) * AST32 + np0 + 4 + tig];
            }
            #pragma unroll
            for (int nf = 0; nf < 4; nf++) {
                int c = cb3 + nf * 8 + g;
                uint32_t b0 = smu[U_XNH + c * XNSTR + np0 + tig];
                uint32_t b1 = smu[U_XNH + c * XNSTR + np0 + 4 + tig];
                #pragma unroll
                for (int mf = 0; mf < 4; mf++)
                    mma_f16(d3[mf][nf], af[mf], b0, b1);
            }
        }
        __syncthreads();   // x/a/L buffers free for next tile
    }

    // ---- commit D3 to global ----
    float* agg = g_agg + (size_t)b * KK * CC;
    #pragma unroll
    for (int mf = 0; mf < 4; mf++) {
        #pragma unroll
        for (int nf = 0; nf < 4; nf++) {
            int k0 = mf * 16 + g;
            int c0 = cb3 + nf * 8 + 2 * tig;
            atomicAdd(&agg[k0 * CC + c0],           d3[mf][nf][0]);
            atomicAdd(&agg[k0 * CC + c0 + 1],       d3[mf][nf][1]);
            atomicAdd(&agg[(k0 + 8) * CC + c0],     d3[mf][nf][2]);
            atomicAdd(&agg[(k0 + 8) * CC + c0 + 1], d3[mf][nf][3]);
        }
    }
    #pragma unroll
    for (int i = 0; i < 16; i++) {
        float v = asum_part[i];
        v += __shfl_xor_sync(0xffffffffu, v, 4);
        v += __shfl_xor_sync(0xffffffffu, v, 8);
        v += __shfl_xor_sync(0xffffffffu, v, 16);
        if (lane < 4)
            atomicAdd(&g_asum[b * KK + sub + 4 * i], v);
    }
}

// ---------------------------------------------------------------------------
__global__ __launch_bounds__(256) void netvlad_finalize(
    const float* __restrict__ centroids,
    float* __restrict__ out)
{
    __shared__ float sred[8];
    const int b = blockIdx.x;
    const int t = threadIdx.x;
    const int lane = t & 31;
    const int w = t >> 5;

    const float* agg = g_agg + (size_t)b * KK * CC;
    const float* as  = g_asum + b * KK;

    float v[8][4];
    float gss = 0.0f;

    #pragma unroll
    for (int r = 0; r < 8; r++) {
        const int k = w * 8 + r;
        const float s = as[k];
        const int c4 = lane * 4;
        float4 a = *(const float4*)&agg[k * CC + c4];
        float4 cn = *(const float4*)&centroids[k * CC + c4];
        v[r][0] = a.x - s * cn.x;
        v[r][1] = a.y - s * cn.y;
        v[r][2] = a.z - s * cn.z;
        v[r][3] = a.w - s * cn.w;
        float ss = v[r][0]*v[r][0] + v[r][1]*v[r][1] + v[r][2]*v[r][2] + v[r][3]*v[r][3];
        #pragma unroll
        for (int off = 16; off > 0; off >>= 1)
            ss += __shfl_xor_sync(0xffffffffu, ss, off);
        float scale = 1.0f / fmaxf(sqrtf(ss), EPSV);
        #pragma unroll
        for (int j = 0; j < 4; j++) { v[r][j] *= scale; gss += v[r][j] * v[r][j]; }
    }

    #pragma unroll
    for (int off = 16; off > 0; off >>= 1)
        gss += __shfl_xor_sync(0xffffffffu, gss, off);
    if (lane == 0) sred[w] = gss;
    __syncthreads();
    float tot = 0.0f;
    #pragma unroll
    for (int i = 0; i < 8; i++) tot += sred[i];
    float gscale = 1.0f / fmaxf(sqrtf(tot), EPSV);

    #pragma unroll
    for (int r = 0; r < 8; r++) {
        const int k = w * 8 + r;
        float4 o;
        o.x = v[r][0] * gscale; o.y = v[r][1] * gscale;
        o.z = v[r][2] * gscale; o.w = v[r][3] * gscale;
        *(float4*)&out[(size_t)b * KK * CC + k * CC + lane * 4] = o;
    }
}

// ---------------------------------------------------------------------------
extern "C" void kernel_launch(void* const* d_in, const int* in_sizes, int n_in,
                              void* d_out, int out_size)
{
    const float* x         = (const float*)d_in[0];
    const float* conv_w    = (const float*)d_in[1];
    const float* conv_b    = (const float*)d_in[2];
    const float* centroids = (const float*)d_in[3];
    float* out = (float*)d_out;

    const int smem_bytes = SMEM_U32 * 4;   // 115712
    static bool attr_set = false;
    if (!attr_set) {
        cudaFuncSetAttribute(netvlad_main,
                             cudaFuncAttributeMaxDynamicSharedMemorySize,
                             smem_bytes);
        attr_set = true;
    }

    zero_scratch<<<264, 1024>>>();
    dim3 grid(SPLITS, BB);
    netvlad_main<<<grid, 256, smem_bytes>>>(x, conv_w, conv_b);
    netvlad_finalize<<<BB, 256>>>(centroids, out);
}

// round 14
// speedup vs baseline: 3.8897x; 1.0691x over previous
#include <cuda_runtime.h>
#include <cuda_fp16.h>
#include <cstdint>

#define BB 32
#define CC 128
#define NN 16384
#define KK 64
#define TN 128
#define SPLITS 32
#define TILES ((NN / SPLITS) / TN)   // 4 tiles per CTA
#define EPSV 1e-12f

// ---- SMEM layout (uint32 units) ----
#define WSTR   68     // W pairs [k=64][cp=64]
#define XCSTR  136    // x c-paired [cp=64][n=128]  (136 mod 32 = 8)
#define XNSTR  68     // x n-paired [c=128][np=64]
#define AST32  68     // a n-paired [k=64][np=64]
#define LDL    68     // logits float [n=128][k=64]
#define U_WH   0
#define U_WL   (U_WH  + 64 * WSTR)     // 4352
#define U_XCH  (U_WL  + 64 * WSTR)     // 8704
#define U_XNH  (U_XCH + 64 * XCSTR)    // 17408
#define U_L    (U_XNH + 128 * XNSTR)   // 26112
#define U_A    (U_L   + 128 * LDL)     // 34816
#define SMEM_U32 (U_A + 64 * AST32)    // 39168 u32 = 156672 B

__device__ __forceinline__ uint32_t pk2u(unsigned short a, unsigned short b) {
    return (uint32_t)a | ((uint32_t)b << 16);
}
__device__ __forceinline__ void hsplit(float x, float& h, float& l) {
    __half hb = __float2half_rn(x);
    h = __half2float(hb);
    l = x - h;
}
__device__ __forceinline__ unsigned short h16(float x) {
    return __half_as_ushort(__float2half_rn(x));
}

__device__ __forceinline__ void mma_f16(float d[4], const uint32_t a[4],
                                        uint32_t b0, uint32_t b1) {
    asm volatile(
        "mma.sync.aligned.m16n8k16.row.col.f32.f16.f16.f32 "
        "{%0,%1,%2,%3},{%4,%5,%6,%7},{%8,%9},{%0,%1,%2,%3};"
        : "+f"(d[0]), "+f"(d[1]), "+f"(d[2]), "+f"(d[3])
        : "r"(a[0]), "r"(a[1]), "r"(a[2]), "r"(a[3]), "r"(b0), "r"(b1));
}

// ---- scratch ----
__device__ float g_agg[BB * KK * CC];
__device__ float g_asum[BB * KK];

__global__ void zero_scratch() {
    int i = blockIdx.x * blockDim.x + threadIdx.x;
    const int tot = BB * KK * CC + BB * KK;
    for (; i < tot; i += gridDim.x * blockDim.x) {
        if (i < BB * KK * CC) g_agg[i] = 0.0f;
        else g_asum[i - BB * KK * CC] = 0.0f;
    }
}

// ---------------------------------------------------------------------------
__global__ __launch_bounds__(256, 1) void netvlad_main(
    const float* __restrict__ x,
    const float* __restrict__ conv_w,
    const float* __restrict__ conv_b)
{
    extern __shared__ uint32_t smu[];

    const int t = threadIdx.x;
    const int wid = t >> 5;
    const int lane = t & 31;
    const int g = lane >> 2;
    const int tig = lane & 3;
    const int b = blockIdx.y;
    const int split = blockIdx.x;

    // phase-1: warp tile 32k x 32n, FULL c contraction (no split)
    const int kb1 = (wid & 1) * 32;
    const int nb1 = (wid >> 1) * 32;   // 0,32,64,96
    // phase-3: warp tile 64k x 32c, 2-way n-contraction split
    const int nh3 = wid >> 2;
    const int cb3 = (wid & 3) * 32;
    // softmax mapping: 4 threads/col, 2 cols/thread
    const int sn2 = t >> 2;            // cols sn2 and sn2+64
    const int sub = t & 3;

    // ---- stage W (hi/lo fp16, c-paired) ----
    {
        const int k = t >> 2;
        const int c8 = (t & 3) * 8;
        #pragma unroll
        for (int p = 0; p < 4; p++) {
            int c = c8 + 32 * p;
            float4 va = *(const float4*)(conv_w + k * CC + c);
            float4 vb = *(const float4*)(conv_w + k * CC + c + 4);
            float h[8], l[8];
            hsplit(va.x, h[0], l[0]); hsplit(va.y, h[1], l[1]);
            hsplit(va.z, h[2], l[2]); hsplit(va.w, h[3], l[3]);
            hsplit(vb.x, h[4], l[4]); hsplit(vb.y, h[5], l[5]);
            hsplit(vb.z, h[6], l[6]); hsplit(vb.w, h[7], l[7]);
            uint4 uh, ul;
            uh.x = pk2u(h16(h[0]), h16(h[1])); uh.y = pk2u(h16(h[2]), h16(h[3]));
            uh.z = pk2u(h16(h[4]), h16(h[5])); uh.w = pk2u(h16(h[6]), h16(h[7]));
            ul.x = pk2u(h16(l[0]), h16(l[1])); ul.y = pk2u(h16(l[2]), h16(l[3]));
            ul.z = pk2u(h16(l[4]), h16(l[5])); ul.w = pk2u(h16(l[6]), h16(l[7]));
            *(uint4*)&smu[U_WH + k * WSTR + c / 2] = uh;
            *(uint4*)&smu[U_WL + k * WSTR + c / 2] = ul;
        }
    }

    float biasr[16];
    #pragma unroll
    for (int i = 0; i < 16; i++) biasr[i] = conv_b[sub + 4 * i];

    float asum_part[16];
    #pragma unroll
    for (int i = 0; i < 16; i++) asum_part[i] = 0.0f;

    float d3[4][4][4];
    #pragma unroll
    for (int mf = 0; mf < 4; mf++)
        #pragma unroll
        for (int nf = 0; nf < 4; nf++)
            #pragma unroll
            for (int q = 0; q < 4; q++) d3[mf][nf][q] = 0.0f;

    const float* xb = x + (size_t)b * CC * NN;
    const int n_base = split * (NN / SPLITS);

    // staging thread mapping: 32 n-lanes x 8 c-rows
    const int cprow = t >> 5;        // 0..7
    const int i4 = (t & 31) * 4;     // n offset 0..124

    // ---- prefetch tile 0: chunk A (c 0-63), chunk B (c 64-127) ----
    float4 pfA[8], pfB[8];
    #pragma unroll
    for (int p = 0; p < 4; p++) {
        int cpA = cprow + 8 * p;
        pfA[2 * p]     = *(const float4*)(xb + (size_t)(2 * cpA) * NN + n_base + i4);
        pfA[2 * p + 1] = *(const float4*)(xb + (size_t)(2 * cpA + 1) * NN + n_base + i4);
        int cpB = 32 + cpA;
        pfB[2 * p]     = *(const float4*)(xb + (size_t)(2 * cpB) * NN + n_base + i4);
        pfB[2 * p + 1] = *(const float4*)(xb + (size_t)(2 * cpB + 1) * NN + n_base + i4);
    }

    __syncthreads();

    for (int tile = 0; tile < TILES; tile++) {
        const int nnext = n_base + (tile + 1) * TN;

        // ---- stage x tile (both chunks) ----
        #pragma unroll
        for (int p = 0; p < 8; p++) {
            int cp = (p < 4) ? (cprow + 8 * p) : (32 + cprow + 8 * (p - 4));
            float4 v0 = (p < 4) ? pfA[2 * p] : pfB[2 * (p - 4)];
            float4 v1 = (p < 4) ? pfA[2 * p + 1] : pfB[2 * (p - 4) + 1];
            unsigned short u0[4], u1[4];
            u0[0] = h16(v0.x); u0[1] = h16(v0.y); u0[2] = h16(v0.z); u0[3] = h16(v0.w);
            u1[0] = h16(v1.x); u1[1] = h16(v1.y); u1[2] = h16(v1.z); u1[3] = h16(v1.w);
            uint4 ch = make_uint4(pk2u(u0[0], u1[0]), pk2u(u0[1], u1[1]),
                                  pk2u(u0[2], u1[2]), pk2u(u0[3], u1[3]));
            *(uint4*)&smu[U_XCH + cp * XCSTR + i4] = ch;
            uint2 nh0 = make_uint2(pk2u(u0[0], u0[1]), pk2u(u0[2], u0[3]));
            uint2 nh1 = make_uint2(pk2u(u1[0], u1[1]), pk2u(u1[2], u1[3]));
            *(uint2*)&smu[U_XNH + (2 * cp) * XNSTR + i4 / 2] = nh0;
            *(uint2*)&smu[U_XNH + (2 * cp + 1) * XNSTR + i4 / 2] = nh1;
        }
        // ---- prefetch next tile chunk A (hides under P1) ----
        if (tile + 1 < TILES) {
            #pragma unroll
            for (int p = 0; p < 4; p++) {
                int cpA = cprow + 8 * p;
                pfA[2 * p]     = *(const float4*)(xb + (size_t)(2 * cpA) * NN + nnext + i4);
                pfA[2 * p + 1] = *(const float4*)(xb + (size_t)(2 * cpA + 1) * NN + nnext + i4);
            }
        }
        __syncthreads();

        // ---- phase 1: D1[k][n] = (Wh + Wl) @ x_hi, full c, B-frag reuse ----
        {
            float d1[2][4][4];
            #pragma unroll
            for (int mf = 0; mf < 2; mf++)
                #pragma unroll
                for (int nf = 0; nf < 4; nf++)
                    #pragma unroll
                    for (int q = 0; q < 4; q++) d1[mf][nf][q] = 0.0f;

            #pragma unroll
            for (int s = 0; s < 8; s++) {
                const int cp0 = s * 8;
                uint32_t afh[2][4], afl[2][4];
                #pragma unroll
                for (int mf = 0; mf < 2; mf++) {
                    int row = kb1 + mf * 16 + g;
                    afh[mf][0] = smu[U_WH + row * WSTR + cp0 + tig];
                    afh[mf][1] = smu[U_WH + (row + 8) * WSTR + cp0 + tig];
                    afh[mf][2] = smu[U_WH + row * WSTR + cp0 + 4 + tig];
                    afh[mf][3] = smu[U_WH + (row + 8) * WSTR + cp0 + 4 + tig];
                    afl[mf][0] = smu[U_WL + row * WSTR + cp0 + tig];
                    afl[mf][1] = smu[U_WL + (row + 8) * WSTR + cp0 + tig];
                    afl[mf][2] = smu[U_WL + row * WSTR + cp0 + 4 + tig];
                    afl[mf][3] = smu[U_WL + (row + 8) * WSTR + cp0 + 4 + tig];
                }
                #pragma unroll
                for (int nf = 0; nf < 4; nf++) {
                    int col = nb1 + nf * 8 + g;
                    uint32_t b0 = smu[U_XCH + (cp0 + tig) * XCSTR + col];
                    uint32_t b1 = smu[U_XCH + (cp0 + 4 + tig) * XCSTR + col];
                    mma_f16(d1[0][nf], afh[0], b0, b1);
                    mma_f16(d1[1][nf], afh[1], b0, b1);
                    mma_f16(d1[0][nf], afl[0], b0, b1);
                    mma_f16(d1[1][nf], afl[1], b0, b1);
                }
            }
            float* sL = (float*)&smu[U_L];
            #pragma unroll
            for (int mf = 0; mf < 2; mf++) {
                #pragma unroll
                for (int nf = 0; nf < 4; nf++) {
                    int kk = kb1 + mf * 16 + g;
                    int nn = nb1 + nf * 8 + 2 * tig;
                    sL[nn * LDL + kk]           = d1[mf][nf][0];
                    sL[(nn + 1) * LDL + kk]     = d1[mf][nf][1];
                    sL[nn * LDL + kk + 8]       = d1[mf][nf][2];
                    sL[(nn + 1) * LDL + kk + 8] = d1[mf][nf][3];
                }
            }
        }
        __syncthreads();

        // ---- softmax(relu) over k; 2 columns per thread ----
        {
            const float* sL = (const float*)&smu[U_L];
            unsigned short* aP = (unsigned short*)&smu[U_A];
            #pragma unroll
            for (int h = 0; h < 2; h++) {
                const int col = sn2 + 64 * h;
                float av[16];
                float s = 0.0f;
                #pragma unroll
                for (int i = 0; i < 16; i++) {
                    int k = sub + 4 * i;
                    float v = sL[col * LDL + k] + biasr[i];
                    av[i] = __expf(fmaxf(v, 0.0f));
                    s += av[i];
                }
                s += __shfl_xor_sync(0xffffffffu, s, 1);
                s += __shfl_xor_sync(0xffffffffu, s, 2);
                float inv = 1.0f / s;
                #pragma unroll
                for (int i = 0; i < 16; i++) {
                    int k = sub + 4 * i;
                    float a = av[i] * inv;
                    asum_part[i] += a;
                    aP[k * (2 * AST32) + col] = h16(a);
                }
            }
        }
        // ---- prefetch next tile chunk B (hides under P3) ----
        if (tile + 1 < TILES) {
            #pragma unroll
            for (int p = 0; p < 4; p++) {
                int cpB = 32 + cprow + 8 * p;
                pfB[2 * p]     = *(const float4*)(xb + (size_t)(2 * cpB) * NN + nnext + i4);
                pfB[2 * p + 1] = *(const float4*)(xb + (size_t)(2 * cpB + 1) * NN + nnext + i4);
            }
        }
        __syncthreads();

        // ---- phase 3: D3[k][c] += a @ x^T; single fp16 pass ----
        #pragma unroll
        for (int s = 0; s < 4; s++) {
            const int np0 = nh3 * 32 + s * 8;
            uint32_t af[4][4];
            #pragma unroll
            for (int mf = 0; mf < 4; mf++) {
                int row = mf * 16 + g;
                af[mf][0] = smu[U_A + row * AST32 + np0 + tig];
                af[mf][1] = smu[U_A + (row + 8) * AST32 + np0 + tig];
                af[mf][2] = smu[U_A + row * AST32 + np0 + 4 + tig];
                af[mf][3] = smu[U_A + (row + 8) * AST32 + np0 + 4 + tig];
            }
            #pragma unroll
            for (int nf = 0; nf < 4; nf++) {
                int c = cb3 + nf * 8 + g;
                uint32_t b0 = smu[U_XNH + c * XNSTR + np0 + tig];
                uint32_t b1 = smu[U_XNH + c * XNSTR + np0 + 4 + tig];
                #pragma unroll
                for (int mf = 0; mf < 4; mf++)
                    mma_f16(d3[mf][nf], af[mf], b0, b1);
            }
        }
        __syncthreads();   // protect staging writes of t+1 vs P3 reads of t
    }

    // ---- commit D3 to global (both n-halves add same addrs via atomics) ----
    float* agg = g_agg + (size_t)b * KK * CC;
    #pragma unroll
    for (int mf = 0; mf < 4; mf++) {
        #pragma unroll
        for (int nf = 0; nf < 4; nf++) {
            int k0 = mf * 16 + g;
            int c0 = cb3 + nf * 8 + 2 * tig;
            atomicAdd(&agg[k0 * CC + c0],           d3[mf][nf][0]);
            atomicAdd(&agg[k0 * CC + c0 + 1],       d3[mf][nf][1]);
            atomicAdd(&agg[(k0 + 8) * CC + c0],     d3[mf][nf][2]);
            atomicAdd(&agg[(k0 + 8) * CC + c0 + 1], d3[mf][nf][3]);
        }
    }
    #pragma unroll
    for (int i = 0; i < 16; i++) {
        float v = asum_part[i];
        v += __shfl_xor_sync(0xffffffffu, v, 4);
        v += __shfl_xor_sync(0xffffffffu, v, 8);
        v += __shfl_xor_sync(0xffffffffu, v, 16);
        if (lane < 4)
            atomicAdd(&g_asum[b * KK + sub + 4 * i], v);
    }
}

// ---------------------------------------------------------------------------
__global__ __launch_bounds__(256) void netvlad_finalize(
    const float* __restrict__ centroids,
    float* __restrict__ out)
{
    __shared__ float sred[8];
    const int b = blockIdx.x;
    const int t = threadIdx.x;
    const int lane = t & 31;
    const int w = t >> 5;

    const float* agg = g_agg + (size_t)b * KK * CC;
    const float* as  = g_asum + b * KK;

    float v[8][4];
    float gss = 0.0f;

    #pragma unroll
    for (int r = 0; r < 8; r++) {
        const int k = w * 8 + r;
        const float s = as[k];
        const int c4 = lane * 4;
        float4 a = *(const float4*)&agg[k * CC + c4];
        float4 cn = *(const float4*)&centroids[k * CC + c4];
        v[r][0] = a.x - s * cn.x;
        v[r][1] = a.y - s * cn.y;
        v[r][2] = a.z - s * cn.z;
        v[r][3] = a.w - s * cn.w;
        float ss = v[r][0]*v[r][0] + v[r][1]*v[r][1] + v[r][2]*v[r][2] + v[r][3]*v[r][3];
        #pragma unroll
        for (int off = 16; off > 0; off >>= 1)
            ss += __shfl_xor_sync(0xffffffffu, ss, off);
        float scale = 1.0f / fmaxf(sqrtf(ss), EPSV);
        #pragma unroll
        for (int j = 0; j < 4; j++) { v[r][j] *= scale; gss += v[r][j] * v[r][j]; }
    }

    #pragma unroll
    for (int off = 16; off > 0; off >>= 1)
        gss += __shfl_xor_sync(0xffffffffu, gss, off);
    if (lane == 0) sred[w] = gss;
    __syncthreads();
    float tot = 0.0f;
    #pragma unroll
    for (int i = 0; i < 8; i++) tot += sred[i];
    float gscale = 1.0f / fmaxf(sqrtf(tot), EPSV);

    #pragma unroll
    for (int r = 0; r < 8; r++) {
        const int k = w * 8 + r;
        float4 o;
        o.x = v[r][0] * gscale; o.y = v[r][1] * gscale;
        o.z = v[r][2] * gscale; o.w = v[r][3] * gscale;
        *(float4*)&out[(size_t)b * KK * CC + k * CC + lane * 4] = o;
    }
}

// ---------------------------------------------------------------------------
extern "C" void kernel_launch(void* const* d_in, const int* in_sizes, int n_in,
                              void* d_out, int out_size)
{
    const float* x         = (const float*)d_in[0];
    const float* conv_w    = (const float*)d_in[1];
    const float* conv_b    = (const float*)d_in[2];
    const float* centroids = (const float*)d_in[3];
    float* out = (float*)d_out;

    const int smem_bytes = SMEM_U32 * 4;   // 156672
    static bool attr_set = false;
    if (!attr_set) {
        cudaFuncSetAttribute(netvlad_main,
                             cudaFuncAttributeMaxDynamicSharedMemorySize,
                             smem_bytes);
        attr_set = true;
    }

    zero_scratch<<<264, 1024>>>();
    dim3 grid(SPLITS, BB);
    netvlad_main<<<grid, 256, smem_bytes>>>(x, conv_w, conv_b);
    netvlad_finalize<<<BB, 256>>>(centroids, out);
}